// round 2
// baseline (speedup 1.0000x reference)
#include <cuda_runtime.h>
#include <cuda_bf16.h>
#include <cstdint>

#define N_NODES 100000
#define N_EDGES 1600000
#define D_IN    128
#define D_OUT   64

// Scratch for support = X @ W  (25.6 MB). Static device array: no allocs allowed.
__device__ float g_support[(size_t)N_NODES * D_OUT];

// ---------------------------------------------------------------------------
// Packed fp32x2 helpers (sm_103a FFMA2 path — PTX-only, not emitted from C++)
// ---------------------------------------------------------------------------
__device__ __forceinline__ uint64_t pack2(float lo, float hi) {
    uint64_t r;
    asm("mov.b64 %0, {%1, %2};" : "=l"(r) : "f"(lo), "f"(hi));
    return r;
}
__device__ __forceinline__ void unpack2(uint64_t v, float& lo, float& hi) {
    asm("mov.b64 {%0, %1}, %2;" : "=f"(lo), "=f"(hi) : "l"(v));
}
__device__ __forceinline__ void ffma2(uint64_t& acc, uint64_t a, uint64_t b) {
    asm("fma.rn.f32x2 %0, %1, %2, %0;" : "+l"(acc) : "l"(a), "l"(b));
}

// ---------------------------------------------------------------------------
// Kernel 1: support = X @ W  (+ fused out = bias init)
// Block: 256 threads (8 warps). Each warp computes 8 node rows; lane l owns
// output cols l and l+32. Accumulators are packed f32x2 pairs over the K
// dimension: acc = (sum over even k, sum over odd k). Both operand pairs
// (x_k, x_{k+1}) and (w_k, w_{k+1}) come from adjacent float4 components, so
// the packs cost no instructions — pure FFMA2 inner loop at 2x fp32 rate.
// ---------------------------------------------------------------------------
__global__ __launch_bounds__(256) void gcn_gemm_kernel(
    const float* __restrict__ X, const float* __restrict__ W,
    const float* __restrict__ bias, float* __restrict__ out)
{
    __shared__ float WsT[D_OUT][D_IN + 4];   // transposed W, padded rows

    const int tid = threadIdx.x;
    for (int i = tid; i < D_IN * D_OUT; i += 256) {
        int k = i >> 6;      // / D_OUT
        int c = i & 63;      // % D_OUT
        WsT[c][k] = W[i];
    }
    __syncthreads();

    const int warp = tid >> 5;
    const int lane = tid & 31;
    const int nodeBase = (blockIdx.x * 8 + warp) * 8;
    if (nodeBase >= N_NODES) return;   // N_NODES % 8 == 0: warps all-valid or all-idle

    const float4* __restrict__ X4 = reinterpret_cast<const float4*>(X);

    uint64_t acc0[8], acc1[8];
    #pragma unroll
    for (int j = 0; j < 8; j++) { acc0[j] = 0ull; acc1[j] = 0ull; }  // (+0.f,+0.f)

    #pragma unroll 4
    for (int k = 0; k < D_IN; k += 4) {
        const float4 w0 = *reinterpret_cast<const float4*>(&WsT[lane][k]);
        const float4 w1 = *reinterpret_cast<const float4*>(&WsT[lane + 32][k]);
        const uint64_t w0lo = pack2(w0.x, w0.y), w0hi = pack2(w0.z, w0.w);
        const uint64_t w1lo = pack2(w1.x, w1.y), w1hi = pack2(w1.z, w1.w);
        #pragma unroll
        for (int j = 0; j < 8; j++) {
            const float4 x = X4[(size_t)(nodeBase + j) * (D_IN / 4) + (k >> 2)];
            const uint64_t xlo = pack2(x.x, x.y);
            const uint64_t xhi = pack2(x.z, x.w);
            ffma2(acc0[j], xlo, w0lo);
            ffma2(acc1[j], xlo, w1lo);
            ffma2(acc0[j], xhi, w0hi);
            ffma2(acc1[j], xhi, w1hi);
        }
    }

    const float b0 = __ldg(bias + lane);
    const float b1 = __ldg(bias + lane + 32);

    #pragma unroll
    for (int j = 0; j < 8; j++) {
        float e, o;
        unpack2(acc0[j], e, o); const float s0 = e + o;
        unpack2(acc1[j], e, o); const float s1 = e + o;
        const size_t off = (size_t)(nodeBase + j) * D_OUT;
        g_support[off + lane]      = s0;
        g_support[off + lane + 32] = s1;
        out[off + lane]      = b0;   // fused bias init (out poisoned before timing)
        out[off + lane + 32] = b1;
    }
}

// ---------------------------------------------------------------------------
// Kernel 2: scatter  out[row[e]] += val[e] * support[col[e]]
// 16 threads per edge, each owns one float4 chunk of the 64-wide row.
// Gather from support is fully coalesced (256 B/edge, L2-resident),
// reduction via red.global.add.v4.f32 (no return value -> no scoreboard stall).
// ---------------------------------------------------------------------------
__global__ __launch_bounds__(256) void gcn_scatter_kernel(
    const int*   __restrict__ row,
    const int*   __restrict__ col,
    const float* __restrict__ val,
    const float4* __restrict__ support4,
    float* __restrict__ out)
{
    const long long idx = (long long)blockIdx.x * 256 + threadIdx.x;
    const long long e = idx >> 4;
    if (e >= N_EDGES) return;
    const int c = (int)(idx & 15);

    const int   r  = __ldg(row + e);
    const int   cc = __ldg(col + e);
    const float v  = __ldg(val + e);

    const float4 s = support4[(size_t)cc * (D_OUT / 4) + c];

    const float a0 = s.x * v;
    const float a1 = s.y * v;
    const float a2 = s.z * v;
    const float a3 = s.w * v;

    float* dst = out + (size_t)r * D_OUT + c * 4;
    asm volatile("red.global.add.v4.f32 [%0], {%1, %2, %3, %4};"
                 :: "l"(dst), "f"(a0), "f"(a1), "f"(a2), "f"(a3)
                 : "memory");
}

// ---------------------------------------------------------------------------
// Launch
// Inputs (metadata order): input_feature f32[100000,128], weight f32[128,64],
// bias f32[64], adj_row i32[1.6M], adj_col i32[1.6M], adj_val f32[1.6M]
// Output: f32[100000,64]
// ---------------------------------------------------------------------------
extern "C" void kernel_launch(void* const* d_in, const int* in_sizes, int n_in,
                              void* d_out, int out_size)
{
    const float* X    = (const float*)d_in[0];
    const float* W    = (const float*)d_in[1];
    const float* bias = (const float*)d_in[2];
    const int*   arow = (const int*)d_in[3];
    const int*   acol = (const int*)d_in[4];
    const float* aval = (const float*)d_in[5];
    float* out = (float*)d_out;

    float* support = nullptr;
    cudaGetSymbolAddress((void**)&support, g_support);

    // 1) support = X @ W, fused with out = bias
    gcn_gemm_kernel<<<(N_NODES + 63) / 64, 256>>>(X, W, bias, out);

    // 2) scatter-add over edges
    {
        const long long total = (long long)N_EDGES * 16;
        const int blocks = (int)((total + 255) / 256);
        gcn_scatter_kernel<<<blocks, 256>>>(
            arow, acol, aval, (const float4*)support, out);
    }
}

// round 4
// speedup vs baseline: 1.1550x; 1.1550x over previous
#include <cuda_runtime.h>
#include <cuda_bf16.h>
#include <cstdint>

#define N_NODES 100000
#define N_EDGES 1600000
#define D_IN    128
#define D_OUT   64
#define TILE_M  128

// ---------------------------------------------------------------------------
// Device scratch (no allocations allowed)
// ---------------------------------------------------------------------------
__device__ float g_support[(size_t)N_NODES * D_OUT];
// Fragment-ordered tf32 hi/lo images of W (B operand): [16 ks][4 npair][32 lane][4 reg]
__device__ uint32_t g_Bh[8192];
__device__ uint32_t g_Bl[8192];

// ---------------------------------------------------------------------------
// tf32 helpers
// ---------------------------------------------------------------------------
__device__ __forceinline__ uint32_t f2tf32(float x) {
    uint32_t r;
    asm("cvt.rna.tf32.f32 %0, %1;" : "=r"(r) : "f"(x));
    return r;
}

// mma.sync m16n8k8 tf32: D += A*B (row.col), accumulate in place
__device__ __forceinline__ void mma_tf32(float* d,
                                         uint32_t a0, uint32_t a1, uint32_t a2, uint32_t a3,
                                         uint32_t b0, uint32_t b1) {
    asm volatile(
        "mma.sync.aligned.m16n8k8.row.col.f32.tf32.tf32.f32 "
        "{%0,%1,%2,%3}, {%4,%5,%6,%7}, {%8,%9}, {%0,%1,%2,%3};"
        : "+f"(d[0]), "+f"(d[1]), "+f"(d[2]), "+f"(d[3])
        : "r"(a0), "r"(a1), "r"(a2), "r"(a3), "r"(b0), "r"(b1));
}

// ---------------------------------------------------------------------------
// Kernel 0: W -> fragment-ordered tf32 hi/lo images (runs once, 8192 elems)
// B fragment mapping (m16n8k8, col-major B): for element (k, n):
//   lane = (n&7)*4 + (k&3);  reg = ((n>>3)&1)*2 + ((k>>2)&1)
//   off  = ((k>>3)*4 + (n>>4))*128 + lane*4 + reg
// ---------------------------------------------------------------------------
__global__ __launch_bounds__(256) void gcn_wprep_kernel(const float* __restrict__ W)
{
    const int idx = blockIdx.x * 256 + threadIdx.x;
    if (idx >= D_IN * D_OUT) return;
    const int k = idx >> 6;
    const int n = idx & 63;
    const float w = W[idx];                    // W[k][n], row-major [128][64]
    const uint32_t hb = f2tf32(w);
    const uint32_t lb = f2tf32(w - __uint_as_float(hb));
    const uint32_t off = (uint32_t)(((k >> 3) * 4 + (n >> 4)) * 128
                       + ((n & 7) * 4 + (k & 3)) * 4
                       + ((n >> 3) & 1) * 2 + ((k >> 2) & 1));
    g_Bh[off] = hb;
    g_Bl[off] = lb;
}

// ---------------------------------------------------------------------------
// Kernel 1: support = X @ W via mma.sync tf32 (3xTF32), fused out = bias.
// CTA: 256 threads (8 warps, 4x2 grid of 32x32 warp tiles), tile 128x64, K=128.
// SMEM (fragment-ordered, all LDS.128 conflict-free):
//   A_hi 64K | A_lo 64K | B_hi 32K | B_lo 32K  = 192KB
// A fragment mapping (m16n8k8 row-major A): for element (r, k):
//   lane = (r&7)*4 + (k&3);  reg = ((r>>3)&1) + ((k>>2)&1)*2
//   off  = ((k>>3)*8 + (r>>4))*128 + lane*4 + reg
// ---------------------------------------------------------------------------
#define SM_A_HI 0
#define SM_A_LO 65536
#define SM_B_HI 131072
#define SM_B_LO 163840
#define SM_TOTAL 196608

__global__ void __launch_bounds__(256, 1) gcn_gemm_kernel(
    const float* __restrict__ X, const float* __restrict__ bias,
    float* __restrict__ out)
{
    extern __shared__ char smem[];
    uint32_t* const Ah = reinterpret_cast<uint32_t*>(smem + SM_A_HI);
    uint32_t* const Al = reinterpret_cast<uint32_t*>(smem + SM_A_LO);

    const int tid  = threadIdx.x;
    const int wid  = tid >> 5;
    const int lane = tid & 31;
    const int tileBase = blockIdx.x * TILE_M;

    // --- Stage B (copy pre-built fragment images) ---
    {
        uint4* bh = reinterpret_cast<uint4*>(smem + SM_B_HI);
        uint4* bl = reinterpret_cast<uint4*>(smem + SM_B_LO);
        const uint4* gh = reinterpret_cast<const uint4*>(g_Bh);
        const uint4* gl = reinterpret_cast<const uint4*>(g_Bl);
        #pragma unroll
        for (int i = tid; i < 2048; i += 256) { bh[i] = gh[i]; bl[i] = gl[i]; }
    }

    // --- Stage A: load X tile (coalesced float4), tf32 hi/lo split, scatter STS ---
    {
        const float4* __restrict__ X4 = reinterpret_cast<const float4*>(X);
        #pragma unroll
        for (int it = 0; it < 16; it++) {
            const int idx = tid + it * 256;       // 0..4095
            const int row = idx >> 5;
            const int c4  = idx & 31;             // k = c4*4 + e
            const int node = tileBase + row;
            float4 x = make_float4(0.f, 0.f, 0.f, 0.f);
            if (node < N_NODES) x = X4[(size_t)node * 32 + c4];

            const uint32_t base = (uint32_t)((((c4 >> 1) * 8 + (row >> 4)) * 32
                                 + (row & 7) * 4) * 4
                                 + ((row >> 3) & 1) + ((c4 & 1) * 2));
            const float xs[4] = {x.x, x.y, x.z, x.w};
            #pragma unroll
            for (int e = 0; e < 4; e++) {
                const uint32_t hb = f2tf32(xs[e]);
                const uint32_t lb = f2tf32(xs[e] - __uint_as_float(hb));
                Ah[base + e * 4] = hb;
                Al[base + e * 4] = lb;
            }
        }
    }
    __syncthreads();

    // --- Main loop: K=128 = 16 k8-steps, all SMEM-resident ---
    const int wm = wid >> 1;    // 0..3  (m quadrant, 32 rows)
    const int wn = wid & 1;     // 0..1  (n half, 32 cols)

    float acc[2][4][4];         // [mfrag16][n8][4]
    #pragma unroll
    for (int i = 0; i < 2; i++)
        #pragma unroll
        for (int j = 0; j < 4; j++)
            #pragma unroll
            for (int q = 0; q < 4; q++) acc[i][j][q] = 0.f;

    const uint4* Ah4 = reinterpret_cast<const uint4*>(smem + SM_A_HI);
    const uint4* Al4 = reinterpret_cast<const uint4*>(smem + SM_A_LO);
    const uint4* Bh4 = reinterpret_cast<const uint4*>(smem + SM_B_HI);
    const uint4* Bl4 = reinterpret_cast<const uint4*>(smem + SM_B_LO);

    #pragma unroll
    for (int ks = 0; ks < 16; ks++) {
        uint4 ah[2], al[2], bh[2], bl[2];
        #pragma unroll
        for (int mf = 0; mf < 2; mf++) {
            const int mt = wm * 2 + mf;
            ah[mf] = Ah4[(ks * 8 + mt) * 32 + lane];
            al[mf] = Al4[(ks * 8 + mt) * 32 + lane];
        }
        #pragma unroll
        for (int p = 0; p < 2; p++) {
            const int np = wn * 2 + p;
            bh[p] = Bh4[(ks * 4 + np) * 32 + lane];
            bl[p] = Bl4[(ks * 4 + np) * 32 + lane];
        }
        #pragma unroll
        for (int mf = 0; mf < 2; mf++) {
            #pragma unroll
            for (int p = 0; p < 2; p++) {
                // n8 sub-frag 0 of pair p: B regs (x,y); sub-frag 1: (z,w)
                float* d0 = acc[mf][p * 2];
                float* d1 = acc[mf][p * 2 + 1];
                mma_tf32(d0, ah[mf].x, ah[mf].y, ah[mf].z, ah[mf].w, bh[p].x, bh[p].y);
                mma_tf32(d0, al[mf].x, al[mf].y, al[mf].z, al[mf].w, bh[p].x, bh[p].y);
                mma_tf32(d0, ah[mf].x, ah[mf].y, ah[mf].z, ah[mf].w, bl[p].x, bl[p].y);
                mma_tf32(d1, ah[mf].x, ah[mf].y, ah[mf].z, ah[mf].w, bh[p].z, bh[p].w);
                mma_tf32(d1, al[mf].x, al[mf].y, al[mf].z, al[mf].w, bh[p].z, bh[p].w);
                mma_tf32(d1, ah[mf].x, ah[mf].y, ah[mf].z, ah[mf].w, bl[p].z, bl[p].w);
            }
        }
    }

    // --- Epilogue: acc -> g_support, bias -> out ---
    // D frag: c0,c1 at (row = groupID, col = 2*(lane%4) +0/+1); c2,c3 at row+8
    #pragma unroll
    for (int mf = 0; mf < 2; mf++) {
        #pragma unroll
        for (int n8 = 0; n8 < 4; n8++) {
            const int col = wn * 32 + n8 * 8 + (lane & 3) * 2;
            const float2 b2 = *reinterpret_cast<const float2*>(&bias[col]);
            const int row0 = tileBase + wm * 32 + mf * 16 + (lane >> 2);
            const int row1 = row0 + 8;
            if (row0 < N_NODES) {
                *reinterpret_cast<float2*>(&g_support[(size_t)row0 * D_OUT + col]) =
                    make_float2(acc[mf][n8][0], acc[mf][n8][1]);
                *reinterpret_cast<float2*>(&out[(size_t)row0 * D_OUT + col]) = b2;
            }
            if (row1 < N_NODES) {
                *reinterpret_cast<float2*>(&g_support[(size_t)row1 * D_OUT + col]) =
                    make_float2(acc[mf][n8][2], acc[mf][n8][3]);
                *reinterpret_cast<float2*>(&out[(size_t)row1 * D_OUT + col]) = b2;
            }
        }
    }
}

// ---------------------------------------------------------------------------
// Kernel 2: scatter  out[row[e]] += val[e] * support[col[e]]   (unchanged)
// ---------------------------------------------------------------------------
__global__ __launch_bounds__(256) void gcn_scatter_kernel(
    const int*   __restrict__ row,
    const int*   __restrict__ col,
    const float* __restrict__ val,
    const float4* __restrict__ support4,
    float* __restrict__ out)
{
    const long long idx = (long long)blockIdx.x * 256 + threadIdx.x;
    const long long e = idx >> 4;
    if (e >= N_EDGES) return;
    const int c = (int)(idx & 15);

    const int   r  = __ldg(row + e);
    const int   cc = __ldg(col + e);
    const float v  = __ldg(val + e);

    const float4 s = support4[(size_t)cc * (D_OUT / 4) + c];

    float* dst = out + (size_t)r * D_OUT + c * 4;
    asm volatile("red.global.add.v4.f32 [%0], {%1, %2, %3, %4};"
                 :: "l"(dst), "f"(s.x * v), "f"(s.y * v), "f"(s.z * v), "f"(s.w * v)
                 : "memory");
}

// ---------------------------------------------------------------------------
// Launch
// ---------------------------------------------------------------------------
extern "C" void kernel_launch(void* const* d_in, const int* in_sizes, int n_in,
                              void* d_out, int out_size)
{
    const float* X    = (const float*)d_in[0];
    const float* W    = (const float*)d_in[1];
    const float* bias = (const float*)d_in[2];
    const int*   arow = (const int*)d_in[3];
    const int*   acol = (const int*)d_in[4];
    const float* aval = (const float*)d_in[5];
    float* out = (float*)d_out;

    float* support = nullptr;
    cudaGetSymbolAddress((void**)&support, g_support);

    cudaFuncSetAttribute(gcn_gemm_kernel,
                         cudaFuncAttributeMaxDynamicSharedMemorySize, SM_TOTAL);

    // 0) W -> tf32 hi/lo fragment images
    gcn_wprep_kernel<<<(D_IN * D_OUT + 255) / 256, 256>>>(W);

    // 1) support = X @ W (mma.sync tf32 3x), fused out = bias
    const int nTiles = (N_NODES + TILE_M - 1) / TILE_M;
    gcn_gemm_kernel<<<nTiles, 256, SM_TOTAL>>>(X, bias, out);

    // 2) scatter-add over edges
    const long long total = (long long)N_EDGES * 16;
    gcn_scatter_kernel<<<(int)((total + 255) / 256), 256>>>(
        arow, acol, aval, (const float4*)support, out);
}

// round 5
// speedup vs baseline: 1.4403x; 1.2469x over previous
#include <cuda_runtime.h>
#include <cuda_bf16.h>
#include <cstdint>

#define N_NODES 100000
#define N_EDGES 1600000
#define D_IN    128
#define D_OUT   64
#define TILE_M  128

// ---------------------------------------------------------------------------
// Device scratch (no allocations allowed)
// ---------------------------------------------------------------------------
__device__ float g_support[(size_t)N_NODES * D_OUT];
// Fragment-ordered tf32 hi/lo images of W (B operand): [16 ks][4 npair][32 lane][4 reg]
__device__ uint32_t g_Bh[8192];
__device__ uint32_t g_Bl[8192];

// ---------------------------------------------------------------------------
// tf32 helpers
// ---------------------------------------------------------------------------
__device__ __forceinline__ uint32_t f2tf32(float x) {
    uint32_t r;
    asm("cvt.rna.tf32.f32 %0, %1;" : "=r"(r) : "f"(x));
    return r;
}

// mma.sync m16n8k8 tf32: D += A*B (row.col), accumulate in place
__device__ __forceinline__ void mma_tf32(float* d,
                                         uint32_t a0, uint32_t a1, uint32_t a2, uint32_t a3,
                                         uint32_t b0, uint32_t b1) {
    asm volatile(
        "mma.sync.aligned.m16n8k8.row.col.f32.tf32.tf32.f32 "
        "{%0,%1,%2,%3}, {%4,%5,%6,%7}, {%8,%9}, {%0,%1,%2,%3};"
        : "+f"(d[0]), "+f"(d[1]), "+f"(d[2]), "+f"(d[3])
        : "r"(a0), "r"(a1), "r"(a2), "r"(a3), "r"(b0), "r"(b1));
}

// ---------------------------------------------------------------------------
// Kernel 0: W -> fragment-ordered tf32 hi/lo images (runs once, 8192 elems)
// B fragment mapping (m16n8k8, col-major B): for element (k, n):
//   lane = (n&7)*4 + (k&3);  reg = ((n>>3)&1)*2 + ((k>>2)&1)
//   off  = ((k>>3)*4 + (n>>4))*128 + lane*4 + reg
// ---------------------------------------------------------------------------
__global__ __launch_bounds__(256) void gcn_wprep_kernel(const float* __restrict__ W)
{
    const int idx = blockIdx.x * 256 + threadIdx.x;
    if (idx >= D_IN * D_OUT) return;
    const int k = idx >> 6;
    const int n = idx & 63;
    const float w = W[idx];                    // W[k][n], row-major [128][64]
    const uint32_t hb = f2tf32(w);
    const uint32_t lb = f2tf32(w - __uint_as_float(hb));
    const uint32_t off = (uint32_t)(((k >> 3) * 4 + (n >> 4)) * 128
                       + ((n & 7) * 4 + (k & 3)) * 4
                       + ((n >> 3) & 1) * 2 + ((k >> 2) & 1));
    g_Bh[off] = hb;
    g_Bl[off] = lb;
}

// ---------------------------------------------------------------------------
// Kernel 1: support = X @ W via mma.sync tf32 (3xTF32), fused out = bias.
// CTA: 256 threads (8 warps, 4x2 grid of 32x32 warp tiles), tile 128x64, K=128.
//
// A fragment storage (hi and lo buffers): group G = mt*16 + ks (ks innermost!),
// each group padded to 132 words (528 B) so the staging STS pattern
// (ks = lane>>1 within a warp) lands on banks 4*(lane>>1) + 2*(lane&1):
// 2-way conflicts instead of the old 16-way (group stride was = 0 mod 32).
// Main-loop reads: lane reads uint4 at G*33 + lane (uint4 units) -> conflict-free.
//
// A fragment mapping (m16n8k8 row-major A): element (r, k):
//   unit U = (r&7)*4 + (k&3);  reg = ((r>>3)&1) + ((k>>2)&1)*2
//   word  = (mt*16 + ks)*132 + U*4 + reg,  mt = r>>4, ks = k>>3
// ---------------------------------------------------------------------------
#define A_GROUP_W 132                     // padded words per fragment group
#define A_BUF_BYTES (128 * A_GROUP_W * 4) // 128 groups -> 67584 B
#define SM_A_HI 0
#define SM_A_LO A_BUF_BYTES
#define SM_B_HI (2 * A_BUF_BYTES)
#define SM_B_LO (2 * A_BUF_BYTES + 32768)
#define SM_TOTAL (2 * A_BUF_BYTES + 65536)   // 200704 B

__global__ void __launch_bounds__(256, 1) gcn_gemm_kernel(
    const float* __restrict__ X, const float* __restrict__ bias,
    float* __restrict__ out)
{
    extern __shared__ char smem[];
    uint32_t* const Ah = reinterpret_cast<uint32_t*>(smem + SM_A_HI);
    uint32_t* const Al = reinterpret_cast<uint32_t*>(smem + SM_A_LO);

    const int tid  = threadIdx.x;
    const int wid  = tid >> 5;
    const int lane = tid & 31;
    const int tileBase = blockIdx.x * TILE_M;

    // --- Stage B (copy pre-built fragment images; linear, conflict-free) ---
    {
        uint4* bh = reinterpret_cast<uint4*>(smem + SM_B_HI);
        uint4* bl = reinterpret_cast<uint4*>(smem + SM_B_LO);
        const uint4* gh = reinterpret_cast<const uint4*>(g_Bh);
        const uint4* gl = reinterpret_cast<const uint4*>(g_Bl);
        #pragma unroll
        for (int i = tid; i < 2048; i += 256) { bh[i] = gh[i]; bl[i] = gl[i]; }
    }

    // --- Stage A: load X tile (coalesced float4), tf32 hi/lo split, scatter STS ---
    {
        const float4* __restrict__ X4 = reinterpret_cast<const float4*>(X);
        #pragma unroll
        for (int it = 0; it < 16; it++) {
            const int idx = tid + it * 256;       // 0..4095
            const int row = idx >> 5;
            const int c4  = idx & 31;             // k = c4*4 + e
            const int node = tileBase + row;
            float4 x = make_float4(0.f, 0.f, 0.f, 0.f);
            if (node < N_NODES) x = X4[(size_t)node * 32 + c4];

            const int mt = row >> 4;
            const int ks = c4 >> 1;
            const uint32_t base = (uint32_t)((mt * 16 + ks) * A_GROUP_W
                                 + (row & 7) * 16
                                 + ((row >> 3) & 1) + (c4 & 1) * 2);
            const float xs[4] = {x.x, x.y, x.z, x.w};
            #pragma unroll
            for (int e = 0; e < 4; e++) {
                const uint32_t hb = f2tf32(xs[e]);
                const uint32_t lb = f2tf32(xs[e] - __uint_as_float(hb));
                Ah[base + e * 4] = hb;
                Al[base + e * 4] = lb;
            }
        }
    }
    __syncthreads();

    // --- Main loop: K=128 = 16 k8-steps, all SMEM-resident ---
    const int wm = wid >> 1;    // 0..3  (m quadrant, 32 rows)
    const int wn = wid & 1;     // 0..1  (n half, 32 cols)

    float acc[2][4][4];         // [mfrag16][n8][4]
    #pragma unroll
    for (int i = 0; i < 2; i++)
        #pragma unroll
        for (int j = 0; j < 4; j++)
            #pragma unroll
            for (int q = 0; q < 4; q++) acc[i][j][q] = 0.f;

    const uint4* Ah4 = reinterpret_cast<const uint4*>(smem + SM_A_HI);
    const uint4* Al4 = reinterpret_cast<const uint4*>(smem + SM_A_LO);
    const uint4* Bh4 = reinterpret_cast<const uint4*>(smem + SM_B_HI);
    const uint4* Bl4 = reinterpret_cast<const uint4*>(smem + SM_B_LO);

    #pragma unroll
    for (int ks = 0; ks < 16; ks++) {
        uint4 ah[2], al[2], bh[2], bl[2];
        #pragma unroll
        for (int mf = 0; mf < 2; mf++) {
            const int mt = wm * 2 + mf;           // 0..7
            ah[mf] = Ah4[(mt * 16 + ks) * (A_GROUP_W / 4) + lane];
            al[mf] = Al4[(mt * 16 + ks) * (A_GROUP_W / 4) + lane];
        }
        #pragma unroll
        for (int p = 0; p < 2; p++) {
            const int np = wn * 2 + p;
            bh[p] = Bh4[(ks * 4 + np) * 32 + lane];
            bl[p] = Bl4[(ks * 4 + np) * 32 + lane];
        }
        #pragma unroll
        for (int mf = 0; mf < 2; mf++) {
            #pragma unroll
            for (int p = 0; p < 2; p++) {
                float* d0 = acc[mf][p * 2];
                float* d1 = acc[mf][p * 2 + 1];
                mma_tf32(d0, ah[mf].x, ah[mf].y, ah[mf].z, ah[mf].w, bh[p].x, bh[p].y);
                mma_tf32(d0, al[mf].x, al[mf].y, al[mf].z, al[mf].w, bh[p].x, bh[p].y);
                mma_tf32(d0, ah[mf].x, ah[mf].y, ah[mf].z, ah[mf].w, bl[p].x, bl[p].y);
                mma_tf32(d1, ah[mf].x, ah[mf].y, ah[mf].z, ah[mf].w, bh[p].z, bh[p].w);
                mma_tf32(d1, al[mf].x, al[mf].y, al[mf].z, al[mf].w, bh[p].z, bh[p].w);
                mma_tf32(d1, ah[mf].x, ah[mf].y, ah[mf].z, ah[mf].w, bl[p].z, bl[p].w);
            }
        }
    }

    // --- Epilogue: acc -> g_support, bias -> out ---
    #pragma unroll
    for (int mf = 0; mf < 2; mf++) {
        #pragma unroll
        for (int n8 = 0; n8 < 4; n8++) {
            const int col = wn * 32 + n8 * 8 + (lane & 3) * 2;
            const float2 b2 = *reinterpret_cast<const float2*>(&bias[col]);
            const int row0 = tileBase + wm * 32 + mf * 16 + (lane >> 2);
            const int row1 = row0 + 8;
            if (row0 < N_NODES) {
                *reinterpret_cast<float2*>(&g_support[(size_t)row0 * D_OUT + col]) =
                    make_float2(acc[mf][n8][0], acc[mf][n8][1]);
                *reinterpret_cast<float2*>(&out[(size_t)row0 * D_OUT + col]) = b2;
            }
            if (row1 < N_NODES) {
                *reinterpret_cast<float2*>(&g_support[(size_t)row1 * D_OUT + col]) =
                    make_float2(acc[mf][n8][2], acc[mf][n8][3]);
                *reinterpret_cast<float2*>(&out[(size_t)row1 * D_OUT + col]) = b2;
            }
        }
    }
}

// ---------------------------------------------------------------------------
// Kernel 2: scatter  out[row[e]] += val[e] * support[col[e]]   (unchanged)
// ---------------------------------------------------------------------------
__global__ __launch_bounds__(256) void gcn_scatter_kernel(
    const int*   __restrict__ row,
    const int*   __restrict__ col,
    const float* __restrict__ val,
    const float4* __restrict__ support4,
    float* __restrict__ out)
{
    const long long idx = (long long)blockIdx.x * 256 + threadIdx.x;
    const long long e = idx >> 4;
    if (e >= N_EDGES) return;
    const int c = (int)(idx & 15);

    const int   r  = __ldg(row + e);
    const int   cc = __ldg(col + e);
    const float v  = __ldg(val + e);

    const float4 s = support4[(size_t)cc * (D_OUT / 4) + c];

    float* dst = out + (size_t)r * D_OUT + c * 4;
    asm volatile("red.global.add.v4.f32 [%0], {%1, %2, %3, %4};"
                 :: "l"(dst), "f"(s.x * v), "f"(s.y * v), "f"(s.z * v), "f"(s.w * v)
                 : "memory");
}

// ---------------------------------------------------------------------------
// Launch
// ---------------------------------------------------------------------------
extern "C" void kernel_launch(void* const* d_in, const int* in_sizes, int n_in,
                              void* d_out, int out_size)
{
    const float* X    = (const float*)d_in[0];
    const float* W    = (const float*)d_in[1];
    const float* bias = (const float*)d_in[2];
    const int*   arow = (const int*)d_in[3];
    const int*   acol = (const int*)d_in[4];
    const float* aval = (const float*)d_in[5];
    float* out = (float*)d_out;

    float* support = nullptr;
    cudaGetSymbolAddress((void**)&support, g_support);

    cudaFuncSetAttribute(gcn_gemm_kernel,
                         cudaFuncAttributeMaxDynamicSharedMemorySize, SM_TOTAL);

    // 0) W -> tf32 hi/lo fragment images
    gcn_wprep_kernel<<<(D_IN * D_OUT + 255) / 256, 256>>>(W);

    // 1) support = X @ W (mma.sync tf32 3x), fused out = bias
    const int nTiles = (N_NODES + TILE_M - 1) / TILE_M;
    gcn_gemm_kernel<<<nTiles, 256, SM_TOTAL>>>(X, bias, out);

    // 2) scatter-add over edges
    const long long total = (long long)N_EDGES * 16;
    gcn_scatter_kernel<<<(int)((total + 255) / 256), 256>>>(
        arow, acol, aval, (const float4*)support, out);
}

// round 6
// speedup vs baseline: 1.8059x; 1.2538x over previous
#include <cuda_runtime.h>
#include <cuda_bf16.h>
#include <cstdint>

#define N_NODES 100000
#define N_EDGES 1600000
#define D_IN    128
#define D_OUT   64
#define TILE_M  128
#define BIN_CAP 32

// ---------------------------------------------------------------------------
// Device scratch (no allocations allowed)
// ---------------------------------------------------------------------------
__device__ float g_support[(size_t)N_NODES * D_OUT];
__device__ uint32_t g_Bh[8192];
__device__ uint32_t g_Bl[8192];
__device__ int   g_cnt[N_NODES + 1];          // [N_NODES] = spill counter
__device__ uint2 g_bin[(size_t)N_NODES * BIN_CAP];   // (col, val bits)
__device__ int   g_spill[N_EDGES];

// ---------------------------------------------------------------------------
// tf32 helpers
// ---------------------------------------------------------------------------
__device__ __forceinline__ uint32_t f2tf32(float x) {
    uint32_t r;
    asm("cvt.rna.tf32.f32 %0, %1;" : "=r"(r) : "f"(x));
    return r;
}

__device__ __forceinline__ void mma_tf32(float* d,
                                         uint32_t a0, uint32_t a1, uint32_t a2, uint32_t a3,
                                         uint32_t b0, uint32_t b1) {
    asm volatile(
        "mma.sync.aligned.m16n8k8.row.col.f32.tf32.tf32.f32 "
        "{%0,%1,%2,%3}, {%4,%5,%6,%7}, {%8,%9}, {%0,%1,%2,%3};"
        : "+f"(d[0]), "+f"(d[1]), "+f"(d[2]), "+f"(d[3])
        : "r"(a0), "r"(a1), "r"(a2), "r"(a3), "r"(b0), "r"(b1));
}

// ---------------------------------------------------------------------------
// Kernel 0: W -> fragment-ordered tf32 hi/lo images
// ---------------------------------------------------------------------------
__global__ __launch_bounds__(256) void gcn_wprep_kernel(const float* __restrict__ W)
{
    const int idx = blockIdx.x * 256 + threadIdx.x;
    if (idx >= D_IN * D_OUT) return;
    const int k = idx >> 6;
    const int n = idx & 63;
    const float w = W[idx];
    const uint32_t hb = f2tf32(w);
    const uint32_t lb = f2tf32(w - __uint_as_float(hb));
    const uint32_t off = (uint32_t)(((k >> 3) * 4 + (n >> 4)) * 128
                       + ((n & 7) * 4 + (k & 3)) * 4
                       + ((n >> 3) & 1) * 2 + ((k >> 2) & 1));
    g_Bh[off] = hb;
    g_Bl[off] = lb;
}

// ---------------------------------------------------------------------------
// Kernel 1: support = X @ W  (3xTF32 mma.sync). Padded A-fragment layout from
// R5 (2-way STS conflicts). out-stores removed — gather writes out now.
// ---------------------------------------------------------------------------
#define A_GROUP_W 132
#define A_BUF_BYTES (128 * A_GROUP_W * 4)
#define SM_A_HI 0
#define SM_A_LO A_BUF_BYTES
#define SM_B_HI (2 * A_BUF_BYTES)
#define SM_B_LO (2 * A_BUF_BYTES + 32768)
#define SM_TOTAL (2 * A_BUF_BYTES + 65536)

__global__ void __launch_bounds__(256, 1) gcn_gemm_kernel(const float* __restrict__ X)
{
    extern __shared__ char smem[];
    uint32_t* const Ah = reinterpret_cast<uint32_t*>(smem + SM_A_HI);
    uint32_t* const Al = reinterpret_cast<uint32_t*>(smem + SM_A_LO);

    const int tid  = threadIdx.x;
    const int wid  = tid >> 5;
    const int lane = tid & 31;
    const int tileBase = blockIdx.x * TILE_M;

    {
        uint4* bh = reinterpret_cast<uint4*>(smem + SM_B_HI);
        uint4* bl = reinterpret_cast<uint4*>(smem + SM_B_LO);
        const uint4* gh = reinterpret_cast<const uint4*>(g_Bh);
        const uint4* gl = reinterpret_cast<const uint4*>(g_Bl);
        #pragma unroll
        for (int i = tid; i < 2048; i += 256) { bh[i] = gh[i]; bl[i] = gl[i]; }
    }

    {
        const float4* __restrict__ X4 = reinterpret_cast<const float4*>(X);
        #pragma unroll
        for (int it = 0; it < 16; it++) {
            const int idx = tid + it * 256;
            const int row = idx >> 5;
            const int c4  = idx & 31;
            const int node = tileBase + row;
            float4 x = make_float4(0.f, 0.f, 0.f, 0.f);
            if (node < N_NODES) x = X4[(size_t)node * 32 + c4];

            const int mt = row >> 4;
            const int ks = c4 >> 1;
            const uint32_t base = (uint32_t)((mt * 16 + ks) * A_GROUP_W
                                 + (row & 7) * 16
                                 + ((row >> 3) & 1) + (c4 & 1) * 2);
            const float xs[4] = {x.x, x.y, x.z, x.w};
            #pragma unroll
            for (int e = 0; e < 4; e++) {
                const uint32_t hb = f2tf32(xs[e]);
                const uint32_t lb = f2tf32(xs[e] - __uint_as_float(hb));
                Ah[base + e * 4] = hb;
                Al[base + e * 4] = lb;
            }
        }
    }
    __syncthreads();

    const int wm = wid >> 1;
    const int wn = wid & 1;

    float acc[2][4][4];
    #pragma unroll
    for (int i = 0; i < 2; i++)
        #pragma unroll
        for (int j = 0; j < 4; j++)
            #pragma unroll
            for (int q = 0; q < 4; q++) acc[i][j][q] = 0.f;

    const uint4* Ah4 = reinterpret_cast<const uint4*>(smem + SM_A_HI);
    const uint4* Al4 = reinterpret_cast<const uint4*>(smem + SM_A_LO);
    const uint4* Bh4 = reinterpret_cast<const uint4*>(smem + SM_B_HI);
    const uint4* Bl4 = reinterpret_cast<const uint4*>(smem + SM_B_LO);

    #pragma unroll
    for (int ks = 0; ks < 16; ks++) {
        uint4 ah[2], al[2], bh[2], bl[2];
        #pragma unroll
        for (int mf = 0; mf < 2; mf++) {
            const int mt = wm * 2 + mf;
            ah[mf] = Ah4[(mt * 16 + ks) * (A_GROUP_W / 4) + lane];
            al[mf] = Al4[(mt * 16 + ks) * (A_GROUP_W / 4) + lane];
        }
        #pragma unroll
        for (int p = 0; p < 2; p++) {
            const int np = wn * 2 + p;
            bh[p] = Bh4[(ks * 4 + np) * 32 + lane];
            bl[p] = Bl4[(ks * 4 + np) * 32 + lane];
        }
        #pragma unroll
        for (int mf = 0; mf < 2; mf++) {
            #pragma unroll
            for (int p = 0; p < 2; p++) {
                float* d0 = acc[mf][p * 2];
                float* d1 = acc[mf][p * 2 + 1];
                mma_tf32(d0, ah[mf].x, ah[mf].y, ah[mf].z, ah[mf].w, bh[p].x, bh[p].y);
                mma_tf32(d0, al[mf].x, al[mf].y, al[mf].z, al[mf].w, bh[p].x, bh[p].y);
                mma_tf32(d0, ah[mf].x, ah[mf].y, ah[mf].z, ah[mf].w, bl[p].x, bl[p].y);
                mma_tf32(d1, ah[mf].x, ah[mf].y, ah[mf].z, ah[mf].w, bh[p].z, bh[p].w);
                mma_tf32(d1, al[mf].x, al[mf].y, al[mf].z, al[mf].w, bh[p].z, bh[p].w);
                mma_tf32(d1, ah[mf].x, ah[mf].y, ah[mf].z, ah[mf].w, bl[p].z, bl[p].w);
            }
        }
    }

    #pragma unroll
    for (int mf = 0; mf < 2; mf++) {
        #pragma unroll
        for (int n8 = 0; n8 < 4; n8++) {
            const int col = wn * 32 + n8 * 8 + (lane & 3) * 2;
            const int row0 = tileBase + wm * 32 + mf * 16 + (lane >> 2);
            const int row1 = row0 + 8;
            if (row0 < N_NODES)
                *reinterpret_cast<float2*>(&g_support[(size_t)row0 * D_OUT + col]) =
                    make_float2(acc[mf][n8][0], acc[mf][n8][1]);
            if (row1 < N_NODES)
                *reinterpret_cast<float2*>(&g_support[(size_t)row1 * D_OUT + col]) =
                    make_float2(acc[mf][n8][2], acc[mf][n8][3]);
        }
    }
}

// ---------------------------------------------------------------------------
// Kernel 2: bin edges by destination row.
// ---------------------------------------------------------------------------
__global__ __launch_bounds__(256) void gcn_bin_kernel(
    const int* __restrict__ row, const int* __restrict__ col,
    const float* __restrict__ val)
{
    const int e = blockIdx.x * 256 + threadIdx.x;
    if (e >= N_EDGES) return;
    const int r = __ldg(row + e);
    const int p = atomicAdd(&g_cnt[r], 1);
    if (p < BIN_CAP) {
        g_bin[(size_t)r * BIN_CAP + p] =
            make_uint2((uint32_t)__ldg(col + e), __float_as_uint(__ldg(val + e)));
    } else {
        const int sp = atomicAdd(&g_cnt[N_NODES], 1);
        g_spill[sp] = e;
    }
}

// ---------------------------------------------------------------------------
// Kernel 3: gather-reduce. 16 threads per node, thread t owns float4 chunk t.
// out[node] = bias + sum_e val_e * support[col_e]   (plain stores, no atomics)
// ---------------------------------------------------------------------------
__global__ __launch_bounds__(256) void gcn_gather_kernel(
    const float4* __restrict__ support4,
    const float*  __restrict__ bias,
    float4* __restrict__ out4)
{
    const int node = blockIdx.x * 16 + (threadIdx.x >> 4);
    const int t = threadIdx.x & 15;
    if (node >= N_NODES) return;

    const int deg = min(__ldg(&g_cnt[node]), BIN_CAP);
    const uint2* __restrict__ bin = &g_bin[(size_t)node * BIN_CAP];

    float4 acc = make_float4(0.f, 0.f, 0.f, 0.f);
    int e = 0;
    for (; e + 2 <= deg; e += 2) {
        const uint4 b2 = *reinterpret_cast<const uint4*>(&bin[e]);  // 2 edges
        const float4 s1 = support4[(size_t)b2.x * 16 + t];
        const float4 s2 = support4[(size_t)b2.z * 16 + t];
        const float v1 = __uint_as_float(b2.y);
        const float v2 = __uint_as_float(b2.w);
        acc.x = fmaf(v1, s1.x, acc.x); acc.y = fmaf(v1, s1.y, acc.y);
        acc.z = fmaf(v1, s1.z, acc.z); acc.w = fmaf(v1, s1.w, acc.w);
        acc.x = fmaf(v2, s2.x, acc.x); acc.y = fmaf(v2, s2.y, acc.y);
        acc.z = fmaf(v2, s2.z, acc.z); acc.w = fmaf(v2, s2.w, acc.w);
    }
    if (e < deg) {
        const uint2 b = bin[e];
        const float4 s = support4[(size_t)b.x * 16 + t];
        const float v = __uint_as_float(b.y);
        acc.x = fmaf(v, s.x, acc.x); acc.y = fmaf(v, s.y, acc.y);
        acc.z = fmaf(v, s.z, acc.z); acc.w = fmaf(v, s.w, acc.w);
    }

    const float4 b4 = *reinterpret_cast<const float4*>(&bias[t * 4]);
    out4[(size_t)node * 16 + t] =
        make_float4(acc.x + b4.x, acc.y + b4.y, acc.z + b4.z, acc.w + b4.w);
}

// ---------------------------------------------------------------------------
// Kernel 4: spill tail (edges beyond BIN_CAP; ~0 in practice). red.add.
// ---------------------------------------------------------------------------
__global__ __launch_bounds__(256) void gcn_spill_kernel(
    const int* __restrict__ row, const int* __restrict__ col,
    const float* __restrict__ val,
    const float4* __restrict__ support4, float* __restrict__ out)
{
    const int n = g_cnt[N_NODES];
    for (int i = blockIdx.x * 256 + threadIdx.x; i < n; i += gridDim.x * 256) {
        const int e = g_spill[i];
        const int r = __ldg(row + e);
        const int c = __ldg(col + e);
        const float v = __ldg(val + e);
        #pragma unroll
        for (int j = 0; j < 16; j++) {
            const float4 s = support4[(size_t)c * 16 + j];
            float* dst = out + (size_t)r * D_OUT + j * 4;
            asm volatile("red.global.add.v4.f32 [%0], {%1, %2, %3, %4};"
                         :: "l"(dst), "f"(s.x * v), "f"(s.y * v), "f"(s.z * v), "f"(s.w * v)
                         : "memory");
        }
    }
}

// ---------------------------------------------------------------------------
// Launch
// ---------------------------------------------------------------------------
extern "C" void kernel_launch(void* const* d_in, const int* in_sizes, int n_in,
                              void* d_out, int out_size)
{
    const float* X    = (const float*)d_in[0];
    const float* W    = (const float*)d_in[1];
    const float* bias = (const float*)d_in[2];
    const int*   arow = (const int*)d_in[3];
    const int*   acol = (const int*)d_in[4];
    const float* aval = (const float*)d_in[5];
    float* out = (float*)d_out;

    float* support = nullptr;
    cudaGetSymbolAddress((void**)&support, g_support);
    int* cnt = nullptr;
    cudaGetSymbolAddress((void**)&cnt, g_cnt);

    cudaFuncSetAttribute(gcn_gemm_kernel,
                         cudaFuncAttributeMaxDynamicSharedMemorySize, SM_TOTAL);

    // 0) W prep + counter reset
    gcn_wprep_kernel<<<(D_IN * D_OUT + 255) / 256, 256>>>(W);
    cudaMemsetAsync(cnt, 0, (N_NODES + 1) * sizeof(int));

    // 1) bin edges by destination row (independent of GEMM)
    gcn_bin_kernel<<<(N_EDGES + 255) / 256, 256>>>(arow, acol, aval);

    // 2) support = X @ W
    const int nTiles = (N_NODES + TILE_M - 1) / TILE_M;
    gcn_gemm_kernel<<<nTiles, 256, SM_TOTAL>>>(X);

    // 3) gather-reduce into out (writes bias too)
    gcn_gather_kernel<<<(N_NODES + 15) / 16, 256>>>(
        (const float4*)support, bias, (float4*)out);

    // 4) spill tail
    gcn_spill_kernel<<<64, 256>>>(arow, acol, aval, (const float4*)support, out);
}

// round 7
// speedup vs baseline: 1.8201x; 1.0079x over previous
#include <cuda_runtime.h>
#include <cuda_bf16.h>
#include <cstdint>

#define N_NODES 100000
#define N_EDGES 1600000
#define D_IN    128
#define D_OUT   64
#define TILE_M  128
#define BIN_CAP 32

// ---------------------------------------------------------------------------
// Device scratch (no allocations allowed)
// ---------------------------------------------------------------------------
__device__ float g_support[(size_t)N_NODES * D_OUT];
__device__ uint32_t g_Bh[8192];
__device__ uint32_t g_Bl[8192];
__device__ int   g_cnt[N_NODES + 1];          // [N_NODES] = spill counter
__device__ uint2 g_bin[(size_t)N_NODES * BIN_CAP];   // (col, val bits)
__device__ int   g_spill[N_EDGES];

// ---------------------------------------------------------------------------
// tf32 helpers
// ---------------------------------------------------------------------------
__device__ __forceinline__ uint32_t f2tf32(float x) {
    uint32_t r;
    asm("cvt.rna.tf32.f32 %0, %1;" : "=r"(r) : "f"(x));
    return r;
}

__device__ __forceinline__ void mma_tf32(float* d,
                                         uint32_t a0, uint32_t a1, uint32_t a2, uint32_t a3,
                                         uint32_t b0, uint32_t b1) {
    asm volatile(
        "mma.sync.aligned.m16n8k8.row.col.f32.tf32.tf32.f32 "
        "{%0,%1,%2,%3}, {%4,%5,%6,%7}, {%8,%9}, {%0,%1,%2,%3};"
        : "+f"(d[0]), "+f"(d[1]), "+f"(d[2]), "+f"(d[3])
        : "r"(a0), "r"(a1), "r"(a2), "r"(a3), "r"(b0), "r"(b1));
}

// ---------------------------------------------------------------------------
// Kernel 0: W -> fragment-ordered tf32 hi/lo images
// ---------------------------------------------------------------------------
__global__ __launch_bounds__(256) void gcn_wprep_kernel(const float* __restrict__ W)
{
    const int idx = blockIdx.x * 256 + threadIdx.x;
    if (idx >= D_IN * D_OUT) return;
    const int k = idx >> 6;
    const int n = idx & 63;
    const float w = W[idx];
    const uint32_t hb = f2tf32(w);
    const uint32_t lb = f2tf32(w - __uint_as_float(hb));
    const uint32_t off = (uint32_t)(((k >> 3) * 4 + (n >> 4)) * 128
                       + ((n & 7) * 4 + (k & 3)) * 4
                       + ((n >> 3) & 1) * 2 + ((k >> 2) & 1));
    g_Bh[off] = hb;
    g_Bl[off] = lb;
}

// ---------------------------------------------------------------------------
// Kernel 1: support = X @ W  (3xTF32 mma.sync, padded fragment SMEM layout)
// ---------------------------------------------------------------------------
#define A_GROUP_W 132
#define A_BUF_BYTES (128 * A_GROUP_W * 4)
#define SM_A_HI 0
#define SM_A_LO A_BUF_BYTES
#define SM_B_HI (2 * A_BUF_BYTES)
#define SM_B_LO (2 * A_BUF_BYTES + 32768)
#define SM_TOTAL (2 * A_BUF_BYTES + 65536)

__global__ void __launch_bounds__(256, 1) gcn_gemm_kernel(const float* __restrict__ X)
{
    extern __shared__ char smem[];
    uint32_t* const Ah = reinterpret_cast<uint32_t*>(smem + SM_A_HI);
    uint32_t* const Al = reinterpret_cast<uint32_t*>(smem + SM_A_LO);

    const int tid  = threadIdx.x;
    const int wid  = tid >> 5;
    const int lane = tid & 31;
    const int tileBase = blockIdx.x * TILE_M;

    {
        uint4* bh = reinterpret_cast<uint4*>(smem + SM_B_HI);
        uint4* bl = reinterpret_cast<uint4*>(smem + SM_B_LO);
        const uint4* gh = reinterpret_cast<const uint4*>(g_Bh);
        const uint4* gl = reinterpret_cast<const uint4*>(g_Bl);
        #pragma unroll
        for (int i = tid; i < 2048; i += 256) { bh[i] = gh[i]; bl[i] = gl[i]; }
    }

    {
        const float4* __restrict__ X4 = reinterpret_cast<const float4*>(X);
        #pragma unroll
        for (int it = 0; it < 16; it++) {
            const int idx = tid + it * 256;
            const int row = idx >> 5;
            const int c4  = idx & 31;
            const int node = tileBase + row;
            float4 x = make_float4(0.f, 0.f, 0.f, 0.f);
            if (node < N_NODES) x = X4[(size_t)node * 32 + c4];

            const int mt = row >> 4;
            const int ks = c4 >> 1;
            const uint32_t base = (uint32_t)((mt * 16 + ks) * A_GROUP_W
                                 + (row & 7) * 16
                                 + ((row >> 3) & 1) + (c4 & 1) * 2);
            const float xs[4] = {x.x, x.y, x.z, x.w};
            #pragma unroll
            for (int e = 0; e < 4; e++) {
                const uint32_t hb = f2tf32(xs[e]);
                const uint32_t lb = f2tf32(xs[e] - __uint_as_float(hb));
                Ah[base + e * 4] = hb;
                Al[base + e * 4] = lb;
            }
        }
    }
    __syncthreads();

    const int wm = wid >> 1;
    const int wn = wid & 1;

    float acc[2][4][4];
    #pragma unroll
    for (int i = 0; i < 2; i++)
        #pragma unroll
        for (int j = 0; j < 4; j++)
            #pragma unroll
            for (int q = 0; q < 4; q++) acc[i][j][q] = 0.f;

    const uint4* Ah4 = reinterpret_cast<const uint4*>(smem + SM_A_HI);
    const uint4* Al4 = reinterpret_cast<const uint4*>(smem + SM_A_LO);
    const uint4* Bh4 = reinterpret_cast<const uint4*>(smem + SM_B_HI);
    const uint4* Bl4 = reinterpret_cast<const uint4*>(smem + SM_B_LO);

    #pragma unroll
    for (int ks = 0; ks < 16; ks++) {
        uint4 ah[2], al[2], bh[2], bl[2];
        #pragma unroll
        for (int mf = 0; mf < 2; mf++) {
            const int mt = wm * 2 + mf;
            ah[mf] = Ah4[(mt * 16 + ks) * (A_GROUP_W / 4) + lane];
            al[mf] = Al4[(mt * 16 + ks) * (A_GROUP_W / 4) + lane];
        }
        #pragma unroll
        for (int p = 0; p < 2; p++) {
            const int np = wn * 2 + p;
            bh[p] = Bh4[(ks * 4 + np) * 32 + lane];
            bl[p] = Bl4[(ks * 4 + np) * 32 + lane];
        }
        #pragma unroll
        for (int mf = 0; mf < 2; mf++) {
            #pragma unroll
            for (int p = 0; p < 2; p++) {
                float* d0 = acc[mf][p * 2];
                float* d1 = acc[mf][p * 2 + 1];
                mma_tf32(d0, ah[mf].x, ah[mf].y, ah[mf].z, ah[mf].w, bh[p].x, bh[p].y);
                mma_tf32(d0, al[mf].x, al[mf].y, al[mf].z, al[mf].w, bh[p].x, bh[p].y);
                mma_tf32(d0, ah[mf].x, ah[mf].y, ah[mf].z, ah[mf].w, bl[p].x, bl[p].y);
                mma_tf32(d1, ah[mf].x, ah[mf].y, ah[mf].z, ah[mf].w, bh[p].z, bh[p].w);
                mma_tf32(d1, al[mf].x, al[mf].y, al[mf].z, al[mf].w, bh[p].z, bh[p].w);
                mma_tf32(d1, ah[mf].x, ah[mf].y, ah[mf].z, ah[mf].w, bl[p].z, bl[p].w);
            }
        }
    }

    #pragma unroll
    for (int mf = 0; mf < 2; mf++) {
        #pragma unroll
        for (int n8 = 0; n8 < 4; n8++) {
            const int col = wn * 32 + n8 * 8 + (lane & 3) * 2;
            const int row0 = tileBase + wm * 32 + mf * 16 + (lane >> 2);
            const int row1 = row0 + 8;
            if (row0 < N_NODES)
                *reinterpret_cast<float2*>(&g_support[(size_t)row0 * D_OUT + col]) =
                    make_float2(acc[mf][n8][0], acc[mf][n8][1]);
            if (row1 < N_NODES)
                *reinterpret_cast<float2*>(&g_support[(size_t)row1 * D_OUT + col]) =
                    make_float2(acc[mf][n8][2], acc[mf][n8][3]);
        }
    }
}

// ---------------------------------------------------------------------------
// Kernel 2: bin edges by destination row.
// ---------------------------------------------------------------------------
__global__ __launch_bounds__(256) void gcn_bin_kernel(
    const int* __restrict__ row, const int* __restrict__ col,
    const float* __restrict__ val)
{
    const int e = blockIdx.x * 256 + threadIdx.x;
    if (e >= N_EDGES) return;
    const int r = __ldg(row + e);
    const int p = atomicAdd(&g_cnt[r], 1);
    if (p < BIN_CAP) {
        g_bin[(size_t)r * BIN_CAP + p] =
            make_uint2((uint32_t)__ldg(col + e), __float_as_uint(__ldg(val + e)));
    } else {
        const int sp = atomicAdd(&g_cnt[N_NODES], 1);
        g_spill[sp] = e;
    }
}

// ---------------------------------------------------------------------------
// Kernel 3: gather-reduce. 16 threads per node, thread t owns float4 chunk t.
// ---------------------------------------------------------------------------
__global__ __launch_bounds__(256) void gcn_gather_kernel(
    const float4* __restrict__ support4,
    const float*  __restrict__ bias,
    float4* __restrict__ out4)
{
    const int node = blockIdx.x * 16 + (threadIdx.x >> 4);
    const int t = threadIdx.x & 15;
    if (node >= N_NODES) return;

    const int deg = min(__ldg(&g_cnt[node]), BIN_CAP);
    const uint2* __restrict__ bin = &g_bin[(size_t)node * BIN_CAP];

    float4 acc = make_float4(0.f, 0.f, 0.f, 0.f);
    int e = 0;
    for (; e + 2 <= deg; e += 2) {
        const uint4 b2 = *reinterpret_cast<const uint4*>(&bin[e]);
        const float4 s1 = support4[(size_t)b2.x * 16 + t];
        const float4 s2 = support4[(size_t)b2.z * 16 + t];
        const float v1 = __uint_as_float(b2.y);
        const float v2 = __uint_as_float(b2.w);
        acc.x = fmaf(v1, s1.x, acc.x); acc.y = fmaf(v1, s1.y, acc.y);
        acc.z = fmaf(v1, s1.z, acc.z); acc.w = fmaf(v1, s1.w, acc.w);
        acc.x = fmaf(v2, s2.x, acc.x); acc.y = fmaf(v2, s2.y, acc.y);
        acc.z = fmaf(v2, s2.z, acc.z); acc.w = fmaf(v2, s2.w, acc.w);
    }
    if (e < deg) {
        const uint2 b = bin[e];
        const float4 s = support4[(size_t)b.x * 16 + t];
        const float v = __uint_as_float(b.y);
        acc.x = fmaf(v, s.x, acc.x); acc.y = fmaf(v, s.y, acc.y);
        acc.z = fmaf(v, s.z, acc.z); acc.w = fmaf(v, s.w, acc.w);
    }

    const float4 b4 = *reinterpret_cast<const float4*>(&bias[t * 4]);
    out4[(size_t)node * 16 + t] =
        make_float4(acc.x + b4.x, acc.y + b4.y, acc.z + b4.z, acc.w + b4.w);
}

// ---------------------------------------------------------------------------
// Kernel 4: spill tail (edges beyond BIN_CAP; ~0 in practice). red.add.
// ---------------------------------------------------------------------------
__global__ __launch_bounds__(256) void gcn_spill_kernel(
    const int* __restrict__ row, const int* __restrict__ col,
    const float* __restrict__ val,
    const float4* __restrict__ support4, float* __restrict__ out)
{
    const int n = g_cnt[N_NODES];
    for (int i = blockIdx.x * 256 + threadIdx.x; i < n; i += gridDim.x * 256) {
        const int e = g_spill[i];
        const int r = __ldg(row + e);
        const int c = __ldg(col + e);
        const float v = __ldg(val + e);
        #pragma unroll
        for (int j = 0; j < 16; j++) {
            const float4 s = support4[(size_t)c * 16 + j];
            float* dst = out + (size_t)r * D_OUT + j * 4;
            asm volatile("red.global.add.v4.f32 [%0], {%1, %2, %3, %4};"
                         :: "l"(dst), "f"(s.x * v), "f"(s.y * v), "f"(s.z * v), "f"(s.w * v)
                         : "memory");
        }
    }
}

// ---------------------------------------------------------------------------
// Launch — fork/join: [wprep -> GEMM] on main stream concurrent with
// [memset -> bin] on side stream; gather+spill after the join.
// Stream/events created lazily once (objects only; captured work is identical
// on every call).
// ---------------------------------------------------------------------------
extern "C" void kernel_launch(void* const* d_in, const int* in_sizes, int n_in,
                              void* d_out, int out_size)
{
    const float* X    = (const float*)d_in[0];
    const float* W    = (const float*)d_in[1];
    const float* bias = (const float*)d_in[2];
    const int*   arow = (const int*)d_in[3];
    const int*   acol = (const int*)d_in[4];
    const float* aval = (const float*)d_in[5];
    float* out = (float*)d_out;

    float* support = nullptr;
    cudaGetSymbolAddress((void**)&support, g_support);
    int* cnt = nullptr;
    cudaGetSymbolAddress((void**)&cnt, g_cnt);

    static cudaStream_t s2 = nullptr;
    static cudaEvent_t evFork = nullptr, evJoin = nullptr;
    if (s2 == nullptr) {
        cudaStreamCreateWithFlags(&s2, cudaStreamNonBlocking);
        cudaEventCreateWithFlags(&evFork, cudaEventDisableTiming);
        cudaEventCreateWithFlags(&evJoin, cudaEventDisableTiming);
        cudaFuncSetAttribute(gcn_gemm_kernel,
                             cudaFuncAttributeMaxDynamicSharedMemorySize, SM_TOTAL);
    }

    // Fork side branch: memset(cnt) -> bin   (independent of GEMM)
    cudaEventRecord(evFork, 0);
    cudaStreamWaitEvent(s2, evFork, 0);
    cudaMemsetAsync(cnt, 0, (N_NODES + 1) * sizeof(int), s2);
    gcn_bin_kernel<<<(N_EDGES + 255) / 256, 256, 0, s2>>>(arow, acol, aval);
    cudaEventRecord(evJoin, s2);

    // Main branch: wprep -> GEMM
    gcn_wprep_kernel<<<(D_IN * D_OUT + 255) / 256, 256>>>(W);
    const int nTiles = (N_NODES + TILE_M - 1) / TILE_M;
    gcn_gemm_kernel<<<nTiles, 256, SM_TOTAL>>>(X);

    // Join, then gather + spill
    cudaStreamWaitEvent(0, evJoin, 0);
    gcn_gather_kernel<<<(N_NODES + 15) / 16, 256>>>(
        (const float4*)support, bias, (float4*)out);
    gcn_spill_kernel<<<64, 256>>>(arow, acol, aval, (const float4*)support, out);
}

// round 8
// speedup vs baseline: 1.9577x; 1.0756x over previous
#include <cuda_runtime.h>
#include <cuda_bf16.h>
#include <cstdint>

#define N_NODES 100000
#define N_EDGES 1600000
#define D_IN    128
#define D_OUT   64
#define TILE_M  128
#define BIN_CAP 32

// ---------------------------------------------------------------------------
// Device scratch (no allocations allowed)
// ---------------------------------------------------------------------------
__device__ float g_support[(size_t)N_NODES * D_OUT];
__device__ float g_Bf[8192];                  // fragment-ordered fp32 W image
__device__ int   g_cnt[N_NODES + 1];          // [N_NODES] = spill counter
__device__ uint2 g_bin[(size_t)N_NODES * BIN_CAP];   // (col, val bits)
__device__ int   g_spill[N_EDGES];

// ---------------------------------------------------------------------------
// tf32 helpers
// ---------------------------------------------------------------------------
__device__ __forceinline__ uint32_t f2tf32(float x) {
    uint32_t r;
    asm("cvt.rna.tf32.f32 %0, %1;" : "=r"(r) : "f"(x));
    return r;
}
// split fp32 -> (tf32 hi, tf32 lo)
__device__ __forceinline__ void tf32split(float f, uint32_t& h, uint32_t& l) {
    h = f2tf32(f);
    l = f2tf32(f - __uint_as_float(h));
}

__device__ __forceinline__ void mma_tf32(float* d,
                                         uint32_t a0, uint32_t a1, uint32_t a2, uint32_t a3,
                                         uint32_t b0, uint32_t b1) {
    asm volatile(
        "mma.sync.aligned.m16n8k8.row.col.f32.tf32.tf32.f32 "
        "{%0,%1,%2,%3}, {%4,%5,%6,%7}, {%8,%9}, {%0,%1,%2,%3};"
        : "+f"(d[0]), "+f"(d[1]), "+f"(d[2]), "+f"(d[3])
        : "r"(a0), "r"(a1), "r"(a2), "r"(a3), "r"(b0), "r"(b1));
}

// ---------------------------------------------------------------------------
// Kernel 0: W -> fragment-ordered fp32 image (hi/lo split happens in-register
// inside the GEMM now).
// B fragment mapping (m16n8k8 col-major B), element (k, n):
//   lane = (n&7)*4 + (k&3);  reg = ((n>>3)&1)*2 + ((k>>2)&1)
//   off  = ((k>>3)*4 + (n>>4))*128 + lane*4 + reg
// ---------------------------------------------------------------------------
__global__ __launch_bounds__(256) void gcn_wprep_kernel(const float* __restrict__ W)
{
    const int idx = blockIdx.x * 256 + threadIdx.x;
    if (idx >= D_IN * D_OUT) return;
    const int k = idx >> 6;
    const int n = idx & 63;
    const uint32_t off = (uint32_t)(((k >> 3) * 4 + (n >> 4)) * 128
                       + ((n & 7) * 4 + (k & 3)) * 4
                       + ((n >> 3) & 1) * 2 + ((k >> 2) & 1));
    g_Bf[off] = W[idx];
}

// ---------------------------------------------------------------------------
// Kernel 1: support = X @ W  (3xTF32 mma.sync, fp32 fragments in SMEM,
// in-register tf32 split). SMEM ~100KB -> 2 CTAs/SM.
// A fragment group G = mt*16 + ks, padded to 132 words (2-way STS conflicts).
// ---------------------------------------------------------------------------
#define A_GROUP_W 132
#define A_BUF_BYTES (128 * A_GROUP_W * 4)      // 67584
#define SM_B (A_BUF_BYTES)                     // fp32 B image: 32768 B
#define SM_TOTAL (A_BUF_BYTES + 32768)         // 100352 B

__global__ void __launch_bounds__(256, 2) gcn_gemm_kernel(const float* __restrict__ X)
{
    extern __shared__ char smem[];
    float* const Af = reinterpret_cast<float*>(smem);

    const int tid  = threadIdx.x;
    const int wid  = tid >> 5;
    const int lane = tid & 31;
    const int tileBase = blockIdx.x * TILE_M;

    // --- Stage B (fp32 fragment image copy, linear) ---
    {
        uint4* bs = reinterpret_cast<uint4*>(smem + SM_B);
        const uint4* gb = reinterpret_cast<const uint4*>(g_Bf);
        #pragma unroll
        for (int i = tid; i < 2048; i += 256) bs[i] = gb[i];
    }

    // --- Stage A: coalesced float4 loads, fragment-scatter raw fp32 ---
    {
        const float4* __restrict__ X4 = reinterpret_cast<const float4*>(X);
        #pragma unroll
        for (int it = 0; it < 16; it++) {
            const int idx = tid + it * 256;
            const int row = idx >> 5;
            const int c4  = idx & 31;
            const int node = tileBase + row;
            float4 x = make_float4(0.f, 0.f, 0.f, 0.f);
            if (node < N_NODES) x = X4[(size_t)node * 32 + c4];

            const int mt = row >> 4;
            const int ks = c4 >> 1;
            const uint32_t base = (uint32_t)((mt * 16 + ks) * A_GROUP_W
                                 + (row & 7) * 16
                                 + ((row >> 3) & 1) + (c4 & 1) * 2);
            Af[base]      = x.x;
            Af[base + 4]  = x.y;
            Af[base + 8]  = x.z;
            Af[base + 12] = x.w;
        }
    }
    __syncthreads();

    const int wm = wid >> 1;
    const int wn = wid & 1;

    float acc[2][4][4];
    #pragma unroll
    for (int i = 0; i < 2; i++)
        #pragma unroll
        for (int j = 0; j < 4; j++)
            #pragma unroll
            for (int q = 0; q < 4; q++) acc[i][j][q] = 0.f;

    const float4* Af4 = reinterpret_cast<const float4*>(smem);
    const float4* Bf4 = reinterpret_cast<const float4*>(smem + SM_B);

    #pragma unroll
    for (int ks = 0; ks < 16; ks++) {
        // Load fp32 fragments (4 LDS.128 per warp per ks)
        float4 af[2], bf[2];
        #pragma unroll
        for (int mf = 0; mf < 2; mf++) {
            const int mt = wm * 2 + mf;
            af[mf] = Af4[(mt * 16 + ks) * (A_GROUP_W / 4) + lane];
        }
        #pragma unroll
        for (int p = 0; p < 2; p++) {
            const int np = wn * 2 + p;
            bf[p] = Bf4[(ks * 4 + np) * 32 + lane];
        }

        // In-register tf32 hi/lo split
        uint32_t ah[2][4], al[2][4], bh[2][4], bl[2][4];
        #pragma unroll
        for (int mf = 0; mf < 2; mf++) {
            tf32split(af[mf].x, ah[mf][0], al[mf][0]);
            tf32split(af[mf].y, ah[mf][1], al[mf][1]);
            tf32split(af[mf].z, ah[mf][2], al[mf][2]);
            tf32split(af[mf].w, ah[mf][3], al[mf][3]);
        }
        #pragma unroll
        for (int p = 0; p < 2; p++) {
            tf32split(bf[p].x, bh[p][0], bl[p][0]);
            tf32split(bf[p].y, bh[p][1], bl[p][1]);
            tf32split(bf[p].z, bh[p][2], bl[p][2]);
            tf32split(bf[p].w, bh[p][3], bl[p][3]);
        }

        #pragma unroll
        for (int mf = 0; mf < 2; mf++) {
            #pragma unroll
            for (int p = 0; p < 2; p++) {
                float* d0 = acc[mf][p * 2];
                float* d1 = acc[mf][p * 2 + 1];
                mma_tf32(d0, ah[mf][0], ah[mf][1], ah[mf][2], ah[mf][3], bh[p][0], bh[p][1]);
                mma_tf32(d0, al[mf][0], al[mf][1], al[mf][2], al[mf][3], bh[p][0], bh[p][1]);
                mma_tf32(d0, ah[mf][0], ah[mf][1], ah[mf][2], ah[mf][3], bl[p][0], bl[p][1]);
                mma_tf32(d1, ah[mf][0], ah[mf][1], ah[mf][2], ah[mf][3], bh[p][2], bh[p][3]);
                mma_tf32(d1, al[mf][0], al[mf][1], al[mf][2], al[mf][3], bh[p][2], bh[p][3]);
                mma_tf32(d1, ah[mf][0], ah[mf][1], ah[mf][2], ah[mf][3], bl[p][2], bl[p][3]);
            }
        }
    }

    #pragma unroll
    for (int mf = 0; mf < 2; mf++) {
        #pragma unroll
        for (int n8 = 0; n8 < 4; n8++) {
            const int col = wn * 32 + n8 * 8 + (lane & 3) * 2;
            const int row0 = tileBase + wm * 32 + mf * 16 + (lane >> 2);
            const int row1 = row0 + 8;
            if (row0 < N_NODES)
                *reinterpret_cast<float2*>(&g_support[(size_t)row0 * D_OUT + col]) =
                    make_float2(acc[mf][n8][0], acc[mf][n8][1]);
            if (row1 < N_NODES)
                *reinterpret_cast<float2*>(&g_support[(size_t)row1 * D_OUT + col]) =
                    make_float2(acc[mf][n8][2], acc[mf][n8][3]);
        }
    }
}

// ---------------------------------------------------------------------------
// Kernel 2: bin edges by destination row.
// ---------------------------------------------------------------------------
__global__ __launch_bounds__(256) void gcn_bin_kernel(
    const int* __restrict__ row, const int* __restrict__ col,
    const float* __restrict__ val)
{
    const int e = blockIdx.x * 256 + threadIdx.x;
    if (e >= N_EDGES) return;
    const int r = __ldg(row + e);
    const int p = atomicAdd(&g_cnt[r], 1);
    if (p < BIN_CAP) {
        g_bin[(size_t)r * BIN_CAP + p] =
            make_uint2((uint32_t)__ldg(col + e), __float_as_uint(__ldg(val + e)));
    } else {
        const int sp = atomicAdd(&g_cnt[N_NODES], 1);
        g_spill[sp] = e;
    }
}

// ---------------------------------------------------------------------------
// Kernel 3: gather-reduce. 16 threads per node, thread t owns float4 chunk t.
// ---------------------------------------------------------------------------
__global__ __launch_bounds__(256) void gcn_gather_kernel(
    const float4* __restrict__ support4,
    const float*  __restrict__ bias,
    float4* __restrict__ out4)
{
    const int node = blockIdx.x * 16 + (threadIdx.x >> 4);
    const int t = threadIdx.x & 15;
    if (node >= N_NODES) return;

    const int deg = min(__ldg(&g_cnt[node]), BIN_CAP);
    const uint2* __restrict__ bin = &g_bin[(size_t)node * BIN_CAP];

    float4 acc = make_float4(0.f, 0.f, 0.f, 0.f);
    int e = 0;
    for (; e + 2 <= deg; e += 2) {
        const uint4 b2 = *reinterpret_cast<const uint4*>(&bin[e]);
        const float4 s1 = support4[(size_t)b2.x * 16 + t];
        const float4 s2 = support4[(size_t)b2.z * 16 + t];
        const float v1 = __uint_as_float(b2.y);
        const float v2 = __uint_as_float(b2.w);
        acc.x = fmaf(v1, s1.x, acc.x); acc.y = fmaf(v1, s1.y, acc.y);
        acc.z = fmaf(v1, s1.z, acc.z); acc.w = fmaf(v1, s1.w, acc.w);
        acc.x = fmaf(v2, s2.x, acc.x); acc.y = fmaf(v2, s2.y, acc.y);
        acc.z = fmaf(v2, s2.z, acc.z); acc.w = fmaf(v2, s2.w, acc.w);
    }
    if (e < deg) {
        const uint2 b = bin[e];
        const float4 s = support4[(size_t)b.x * 16 + t];
        const float v = __uint_as_float(b.y);
        acc.x = fmaf(v, s.x, acc.x); acc.y = fmaf(v, s.y, acc.y);
        acc.z = fmaf(v, s.z, acc.z); acc.w = fmaf(v, s.w, acc.w);
    }

    const float4 b4 = *reinterpret_cast<const float4*>(&bias[t * 4]);
    out4[(size_t)node * 16 + t] =
        make_float4(acc.x + b4.x, acc.y + b4.y, acc.z + b4.z, acc.w + b4.w);
}

// ---------------------------------------------------------------------------
// Kernel 4: spill tail (edges beyond BIN_CAP; ~0 in practice). red.add.
// ---------------------------------------------------------------------------
__global__ __launch_bounds__(256) void gcn_spill_kernel(
    const int* __restrict__ row, const int* __restrict__ col,
    const float* __restrict__ val,
    const float4* __restrict__ support4, float* __restrict__ out)
{
    const int n = g_cnt[N_NODES];
    for (int i = blockIdx.x * 256 + threadIdx.x; i < n; i += gridDim.x * 256) {
        const int e = g_spill[i];
        const int r = __ldg(row + e);
        const int c = __ldg(col + e);
        const float v = __ldg(val + e);
        #pragma unroll
        for (int j = 0; j < 16; j++) {
            const float4 s = support4[(size_t)c * 16 + j];
            float* dst = out + (size_t)r * D_OUT + j * 4;
            asm volatile("red.global.add.v4.f32 [%0], {%1, %2, %3, %4};"
                         :: "l"(dst), "f"(s.x * v), "f"(s.y * v), "f"(s.z * v), "f"(s.w * v)
                         : "memory");
        }
    }
}

// ---------------------------------------------------------------------------
// Launch — fork/join: [wprep -> GEMM] || [memset -> bin], then gather+spill.
// ---------------------------------------------------------------------------
extern "C" void kernel_launch(void* const* d_in, const int* in_sizes, int n_in,
                              void* d_out, int out_size)
{
    const float* X    = (const float*)d_in[0];
    const float* W    = (const float*)d_in[1];
    const float* bias = (const float*)d_in[2];
    const int*   arow = (const int*)d_in[3];
    const int*   acol = (const int*)d_in[4];
    const float* aval = (const float*)d_in[5];
    float* out = (float*)d_out;

    float* support = nullptr;
    cudaGetSymbolAddress((void**)&support, g_support);
    int* cnt = nullptr;
    cudaGetSymbolAddress((void**)&cnt, g_cnt);

    static cudaStream_t s2 = nullptr;
    static cudaEvent_t evFork = nullptr, evJoin = nullptr;
    if (s2 == nullptr) {
        cudaStreamCreateWithFlags(&s2, cudaStreamNonBlocking);
        cudaEventCreateWithFlags(&evFork, cudaEventDisableTiming);
        cudaEventCreateWithFlags(&evJoin, cudaEventDisableTiming);
        cudaFuncSetAttribute(gcn_gemm_kernel,
                             cudaFuncAttributeMaxDynamicSharedMemorySize, SM_TOTAL);
    }

    // Fork side branch: memset(cnt) -> bin
    cudaEventRecord(evFork, 0);
    cudaStreamWaitEvent(s2, evFork, 0);
    cudaMemsetAsync(cnt, 0, (N_NODES + 1) * sizeof(int), s2);
    gcn_bin_kernel<<<(N_EDGES + 255) / 256, 256, 0, s2>>>(arow, acol, aval);
    cudaEventRecord(evJoin, s2);

    // Main branch: wprep -> GEMM
    gcn_wprep_kernel<<<(D_IN * D_OUT + 255) / 256, 256>>>(W);
    const int nTiles = (N_NODES + TILE_M - 1) / TILE_M;
    gcn_gemm_kernel<<<nTiles, 256, SM_TOTAL>>>(X);

    // Join, then gather + spill
    cudaStreamWaitEvent(0, evJoin, 0);
    gcn_gather_kernel<<<(N_NODES + 15) / 16, 256>>>(
        (const float4*)support, bias, (float4*)out);
    gcn_spill_kernel<<<64, 256>>>(arow, acol, aval, (const float4*)support, out);
}

// round 9
// speedup vs baseline: 2.1275x; 1.0868x over previous
#include <cuda_runtime.h>
#include <cuda_bf16.h>
#include <cuda_fp16.h>
#include <cstdint>

#define N_NODES 100000
#define N_EDGES 1600000
#define D_IN    128
#define D_OUT   64
#define TILE_M  128
#define BIN_CAP 32

// ---------------------------------------------------------------------------
// Device scratch (no allocations allowed)
// ---------------------------------------------------------------------------
__device__ __half g_supH[(size_t)N_NODES * D_OUT];   // fp16 support
__device__ uint32_t g_BhW[4096];   // fragment-ordered bf16x2 hi image of W
__device__ uint32_t g_BlW[4096];   // fragment-ordered bf16x2 lo image of W
__device__ int   g_cnt[N_NODES + 1];
__device__ uint2 g_bin[(size_t)N_NODES * BIN_CAP];
__device__ int   g_spill[N_EDGES];

// ---------------------------------------------------------------------------
// helpers
// ---------------------------------------------------------------------------
__device__ __forceinline__ uint32_t pack_bf16(float a, float b) {
    __nv_bfloat162 t = __floats2bfloat162_rn(a, b);
    return *reinterpret_cast<uint32_t*>(&t);
}
__device__ __forceinline__ void bf16split(float x, float& hf, float& lf) {
    const __nv_bfloat16 h = __float2bfloat16_rn(x);
    hf = __bfloat162float(h);
    lf = x - hf;
}

// mma.sync m16n8k16 bf16: D += A*B (row.col)
__device__ __forceinline__ void mma_bf16(float* d,
                                         uint32_t a0, uint32_t a1, uint32_t a2, uint32_t a3,
                                         uint32_t b0, uint32_t b1) {
    asm volatile(
        "mma.sync.aligned.m16n8k16.row.col.f32.bf16.bf16.f32 "
        "{%0,%1,%2,%3}, {%4,%5,%6,%7}, {%8,%9}, {%0,%1,%2,%3};"
        : "+f"(d[0]), "+f"(d[1]), "+f"(d[2]), "+f"(d[3])
        : "r"(a0), "r"(a1), "r"(a2), "r"(a3), "r"(b0), "r"(b1));
}

// ---------------------------------------------------------------------------
// Kernel 0: W -> fragment-ordered bf16x2 hi/lo images.
// B fragment (m16n8k16 col-major), element (k, n), k-pair kp = k>>1:
//   lane = (n&7)*4 + (kp&3); reg = ((kp>>2)&1) + 2*((n>>3)&1)
//   group = (k>>4)*4 + (n>>4); word = group*128 + lane*4 + reg
// Each thread handles one (kp, n): packs bf16x2 over the k-pair.
// ---------------------------------------------------------------------------
__global__ __launch_bounds__(256) void gcn_wprep_kernel(const float* __restrict__ W)
{
    const int idx = blockIdx.x * 256 + threadIdx.x;   // 0..4095
    if (idx >= (D_IN / 2) * D_OUT) return;
    const int kp = idx >> 6;       // 0..63
    const int n  = idx & 63;
    const int k  = kp * 2;
    const float w0 = W[k * D_OUT + n];
    const float w1 = W[(k + 1) * D_OUT + n];
    float h0, l0, h1, l1;
    bf16split(w0, h0, l0);
    bf16split(w1, h1, l1);
    const uint32_t word = (uint32_t)((((k >> 4) * 4 + (n >> 4)) * 128)
                        + ((n & 7) * 4 + (kp & 3)) * 4
                        + ((kp >> 2) & 1) + 2 * ((n >> 3) & 1));
    g_BhW[word] = pack_bf16(h0, h1);
    g_BlW[word] = pack_bf16(l0, l1);
}

// ---------------------------------------------------------------------------
// Kernel 1: support = X @ W  (3xBF16 mma.sync m16n8k16), fp16 epilogue.
// CTA: 256 threads, tile 128x64, K=128 (8 k16-steps). 2 CTAs/SM.
// A fragment group G = mt*8 + ks (mt = row>>4, ks = k>>4), padded to 132
// uint32 words (bf16x2 each). B: 32 groups x 128 words, hi/lo.
// ---------------------------------------------------------------------------
#define A_GROUP_W 132
#define A_BUF_BYTES (64 * A_GROUP_W * 4)     // 64 groups -> 33792 B
#define SM_A_HI 0
#define SM_A_LO A_BUF_BYTES
#define SM_B_HI (2 * A_BUF_BYTES)            // 67584
#define SM_B_LO (2 * A_BUF_BYTES + 16384)
#define SM_TOTAL (2 * A_BUF_BYTES + 32768)   // 100352 B

__global__ void __launch_bounds__(256, 2) gcn_gemm_kernel(const float* __restrict__ X)
{
    extern __shared__ char smem[];
    uint32_t* const Ah = reinterpret_cast<uint32_t*>(smem + SM_A_HI);
    uint32_t* const Al = reinterpret_cast<uint32_t*>(smem + SM_A_LO);

    const int tid  = threadIdx.x;
    const int wid  = tid >> 5;
    const int lane = tid & 31;
    const int tileBase = blockIdx.x * TILE_M;

    // --- Stage B (bf16x2 fragment image copy, linear) ---
    {
        uint4* bh = reinterpret_cast<uint4*>(smem + SM_B_HI);
        uint4* bl = reinterpret_cast<uint4*>(smem + SM_B_LO);
        const uint4* gh = reinterpret_cast<const uint4*>(g_BhW);
        const uint4* gl = reinterpret_cast<const uint4*>(g_BlW);
        #pragma unroll
        for (int i = tid; i < 1024; i += 256) { bh[i] = gh[i]; bl[i] = gl[i]; }
    }

    // --- Stage A: coalesced float4 loads, bf16 hi/lo split, fragment STS ---
    // A fragment (m16n8k16 row-major), element (r, k), kp = k>>1:
    //   lane = (r&7)*4 + (kp&3); reg = ((r>>3)&1) + 2*((k&15)>>3)
    //   word = (mt*8 + ks)*132 + lane*4 + reg
    {
        const float4* __restrict__ X4 = reinterpret_cast<const float4*>(X);
        #pragma unroll
        for (int it = 0; it < 16; it++) {
            const int idx = tid + it * 256;
            const int row = idx >> 5;
            const int c4  = idx & 31;            // k = 4*c4 .. 4*c4+3
            const int node = tileBase + row;
            float4 x = make_float4(0.f, 0.f, 0.f, 0.f);
            if (node < N_NODES) x = X4[(size_t)node * 32 + c4];

            float h0, l0, h1, l1, h2, l2, h3, l3;
            bf16split(x.x, h0, l0);
            bf16split(x.y, h1, l1);
            bf16split(x.z, h2, l2);
            bf16split(x.w, h3, l3);

            const int mt = row >> 4;
            const int ks = c4 >> 2;
            const int kk = c4 & 3;               // k' = 4*kk within k16 tile
            const uint32_t word = (uint32_t)((mt * 8 + ks) * A_GROUP_W
                                + ((row & 7) * 4 + (kk & 1) * 2) * 4
                                + ((row >> 3) & 1) + 2 * (kk >> 1));
            Ah[word]     = pack_bf16(h0, h1);
            Al[word]     = pack_bf16(l0, l1);
            Ah[word + 4] = pack_bf16(h2, h3);    // next lane slot, same reg
            Al[word + 4] = pack_bf16(l2, l3);
        }
    }
    __syncthreads();

    const int wm = wid >> 1;
    const int wn = wid & 1;

    float acc[2][4][4];
    #pragma unroll
    for (int i = 0; i < 2; i++)
        #pragma unroll
        for (int j = 0; j < 4; j++)
            #pragma unroll
            for (int q = 0; q < 4; q++) acc[i][j][q] = 0.f;

    const uint4* Ah4 = reinterpret_cast<const uint4*>(smem + SM_A_HI);
    const uint4* Al4 = reinterpret_cast<const uint4*>(smem + SM_A_LO);
    const uint4* Bh4 = reinterpret_cast<const uint4*>(smem + SM_B_HI);
    const uint4* Bl4 = reinterpret_cast<const uint4*>(smem + SM_B_LO);

    #pragma unroll
    for (int ks = 0; ks < 8; ks++) {
        uint4 ah[2], al[2], bh[2], bl[2];
        #pragma unroll
        for (int mf = 0; mf < 2; mf++) {
            const int mt = wm * 2 + mf;
            ah[mf] = Ah4[(mt * 8 + ks) * (A_GROUP_W / 4) + lane];
            al[mf] = Al4[(mt * 8 + ks) * (A_GROUP_W / 4) + lane];
        }
        #pragma unroll
        for (int p = 0; p < 2; p++) {
            const int np = wn * 2 + p;
            bh[p] = Bh4[(ks * 4 + np) * 32 + lane];
            bl[p] = Bl4[(ks * 4 + np) * 32 + lane];
        }
        #pragma unroll
        for (int mf = 0; mf < 2; mf++) {
            #pragma unroll
            for (int p = 0; p < 2; p++) {
                float* d0 = acc[mf][p * 2];
                float* d1 = acc[mf][p * 2 + 1];
                // n8-low uses B regs (.x,.y); n8-high uses (.z,.w)
                mma_bf16(d0, ah[mf].x, ah[mf].y, ah[mf].z, ah[mf].w, bh[p].x, bh[p].y);
                mma_bf16(d0, al[mf].x, al[mf].y, al[mf].z, al[mf].w, bh[p].x, bh[p].y);
                mma_bf16(d0, ah[mf].x, ah[mf].y, ah[mf].z, ah[mf].w, bl[p].x, bl[p].y);
                mma_bf16(d1, ah[mf].x, ah[mf].y, ah[mf].z, ah[mf].w, bh[p].z, bh[p].w);
                mma_bf16(d1, al[mf].x, al[mf].y, al[mf].z, al[mf].w, bh[p].z, bh[p].w);
                mma_bf16(d1, ah[mf].x, ah[mf].y, ah[mf].z, ah[mf].w, bl[p].z, bl[p].w);
            }
        }
    }

    // --- Epilogue: acc -> g_supH (fp16) ---
    #pragma unroll
    for (int mf = 0; mf < 2; mf++) {
        #pragma unroll
        for (int n8 = 0; n8 < 4; n8++) {
            const int col = wn * 32 + n8 * 8 + (lane & 3) * 2;
            const int row0 = tileBase + wm * 32 + mf * 16 + (lane >> 2);
            const int row1 = row0 + 8;
            if (row0 < N_NODES) {
                const __half2 h = __floats2half2_rn(acc[mf][n8][0], acc[mf][n8][1]);
                *reinterpret_cast<uint32_t*>(&g_supH[(size_t)row0 * D_OUT + col]) =
                    *reinterpret_cast<const uint32_t*>(&h);
            }
            if (row1 < N_NODES) {
                const __half2 h = __floats2half2_rn(acc[mf][n8][2], acc[mf][n8][3]);
                *reinterpret_cast<uint32_t*>(&g_supH[(size_t)row1 * D_OUT + col]) =
                    *reinterpret_cast<const uint32_t*>(&h);
            }
        }
    }
}

// ---------------------------------------------------------------------------
// Kernel 2: bin edges by destination row.
// ---------------------------------------------------------------------------
__global__ __launch_bounds__(256) void gcn_bin_kernel(
    const int* __restrict__ row, const int* __restrict__ col,
    const float* __restrict__ val)
{
    const int e = blockIdx.x * 256 + threadIdx.x;
    if (e >= N_EDGES) return;
    const int r = __ldg(row + e);
    const int p = atomicAdd(&g_cnt[r], 1);
    if (p < BIN_CAP) {
        g_bin[(size_t)r * BIN_CAP + p] =
            make_uint2((uint32_t)__ldg(col + e), __float_as_uint(__ldg(val + e)));
    } else {
        const int sp = atomicAdd(&g_cnt[N_NODES], 1);
        g_spill[sp] = e;
    }
}

// ---------------------------------------------------------------------------
// Kernel 3: gather-reduce over fp16 support. 16 threads/node, thread t owns
// 4 output cols (one uint2 = 4 halfs per edge). Accumulate fp32, add bias.
// ---------------------------------------------------------------------------
__global__ __launch_bounds__(256) void gcn_gather_kernel(
    const float* __restrict__ bias,
    float4* __restrict__ out4)
{
    const int node = blockIdx.x * 16 + (threadIdx.x >> 4);
    const int t = threadIdx.x & 15;
    if (node >= N_NODES) return;

    const int deg = min(__ldg(&g_cnt[node]), BIN_CAP);
    const uint2* __restrict__ bin = &g_bin[(size_t)node * BIN_CAP];
    const uint2* __restrict__ sup2 = reinterpret_cast<const uint2*>(g_supH);

    float4 acc = make_float4(0.f, 0.f, 0.f, 0.f);
    int e = 0;
    for (; e + 2 <= deg; e += 2) {
        const uint4 b2 = *reinterpret_cast<const uint4*>(&bin[e]);
        const uint2 u1 = sup2[(size_t)b2.x * 16 + t];
        const uint2 u2 = sup2[(size_t)b2.z * 16 + t];
        const float v1 = __uint_as_float(b2.y);
        const float v2 = __uint_as_float(b2.w);
        const float2 f1a = __half22float2(*reinterpret_cast<const __half2*>(&u1.x));
        const float2 f1b = __half22float2(*reinterpret_cast<const __half2*>(&u1.y));
        const float2 f2a = __half22float2(*reinterpret_cast<const __half2*>(&u2.x));
        const float2 f2b = __half22float2(*reinterpret_cast<const __half2*>(&u2.y));
        acc.x = fmaf(v1, f1a.x, acc.x); acc.y = fmaf(v1, f1a.y, acc.y);
        acc.z = fmaf(v1, f1b.x, acc.z); acc.w = fmaf(v1, f1b.y, acc.w);
        acc.x = fmaf(v2, f2a.x, acc.x); acc.y = fmaf(v2, f2a.y, acc.y);
        acc.z = fmaf(v2, f2b.x, acc.z); acc.w = fmaf(v2, f2b.y, acc.w);
    }
    if (e < deg) {
        const uint2 b = bin[e];
        const uint2 u = sup2[(size_t)b.x * 16 + t];
        const float v = __uint_as_float(b.y);
        const float2 fa = __half22float2(*reinterpret_cast<const __half2*>(&u.x));
        const float2 fb = __half22float2(*reinterpret_cast<const __half2*>(&u.y));
        acc.x = fmaf(v, fa.x, acc.x); acc.y = fmaf(v, fa.y, acc.y);
        acc.z = fmaf(v, fb.x, acc.z); acc.w = fmaf(v, fb.y, acc.w);
    }

    const float4 b4 = *reinterpret_cast<const float4*>(&bias[t * 4]);
    out4[(size_t)node * 16 + t] =
        make_float4(acc.x + b4.x, acc.y + b4.y, acc.z + b4.z, acc.w + b4.w);
}

// ---------------------------------------------------------------------------
// Kernel 4: spill tail (edges beyond BIN_CAP; ~0 in practice). red.add.
// ---------------------------------------------------------------------------
__global__ __launch_bounds__(256) void gcn_spill_kernel(
    const int* __restrict__ row, const int* __restrict__ col,
    const float* __restrict__ val, float* __restrict__ out)
{
    const int n = g_cnt[N_NODES];
    const uint2* __restrict__ sup2 = reinterpret_cast<const uint2*>(g_supH);
    for (int i = blockIdx.x * 256 + threadIdx.x; i < n; i += gridDim.x * 256) {
        const int e = g_spill[i];
        const int r = __ldg(row + e);
        const int c = __ldg(col + e);
        const float v = __ldg(val + e);
        #pragma unroll
        for (int j = 0; j < 16; j++) {
            const uint2 u = sup2[(size_t)c * 16 + j];
            const float2 fa = __half22float2(*reinterpret_cast<const __half2*>(&u.x));
            const float2 fb = __half22float2(*reinterpret_cast<const __half2*>(&u.y));
            float* dst = out + (size_t)r * D_OUT + j * 4;
            asm volatile("red.global.add.v4.f32 [%0], {%1, %2, %3, %4};"
                         :: "l"(dst), "f"(fa.x * v), "f"(fa.y * v), "f"(fb.x * v), "f"(fb.y * v)
                         : "memory");
        }
    }
}

// ---------------------------------------------------------------------------
// Launch — fork/join kept: [wprep -> GEMM] || [memset -> bin], then gather+spill.
// ---------------------------------------------------------------------------
extern "C" void kernel_launch(void* const* d_in, const int* in_sizes, int n_in,
                              void* d_out, int out_size)
{
    const float* X    = (const float*)d_in[0];
    const float* W    = (const float*)d_in[1];
    const float* bias = (const float*)d_in[2];
    const int*   arow = (const int*)d_in[3];
    const int*   acol = (const int*)d_in[4];
    const float* aval = (const float*)d_in[5];
    float* out = (float*)d_out;

    int* cnt = nullptr;
    cudaGetSymbolAddress((void**)&cnt, g_cnt);

    static cudaStream_t s2 = nullptr;
    static cudaEvent_t evFork = nullptr, evJoin = nullptr;
    if (s2 == nullptr) {
        cudaStreamCreateWithFlags(&s2, cudaStreamNonBlocking);
        cudaEventCreateWithFlags(&evFork, cudaEventDisableTiming);
        cudaEventCreateWithFlags(&evJoin, cudaEventDisableTiming);
        cudaFuncSetAttribute(gcn_gemm_kernel,
                             cudaFuncAttributeMaxDynamicSharedMemorySize, SM_TOTAL);
    }

    // Fork side branch: memset(cnt) -> bin
    cudaEventRecord(evFork, 0);
    cudaStreamWaitEvent(s2, evFork, 0);
    cudaMemsetAsync(cnt, 0, (N_NODES + 1) * sizeof(int), s2);
    gcn_bin_kernel<<<(N_EDGES + 255) / 256, 256, 0, s2>>>(arow, acol, aval);
    cudaEventRecord(evJoin, s2);

    // Main branch: wprep -> GEMM
    gcn_wprep_kernel<<<((D_IN / 2) * D_OUT + 255) / 256, 256>>>(W);
    const int nTiles = (N_NODES + TILE_M - 1) / TILE_M;
    gcn_gemm_kernel<<<nTiles, 256, SM_TOTAL>>>(X);

    // Join, then gather + spill
    cudaStreamWaitEvent(0, evJoin, 0);
    gcn_gather_kernel<<<(N_NODES + 15) / 16, 256>>>(bias, (float4*)out);
    gcn_spill_kernel<<<64, 256>>>(arow, acol, aval, out);
}

// round 10
// speedup vs baseline: 2.5289x; 1.1887x over previous
#include <cuda_runtime.h>
#include <cuda_bf16.h>
#include <cuda_fp16.h>
#include <cstdint>

#define N_NODES 100000
#define N_EDGES 1600000
#define D_IN    128
#define D_OUT   64
#define TILE_M  128
#define BIN_CAP 32

// ---------------------------------------------------------------------------
// Device scratch (no allocations allowed)
// ---------------------------------------------------------------------------
__device__ __half g_supH[(size_t)N_NODES * D_OUT];   // fp16 support
__device__ uint32_t g_BhW[4096];   // fragment-ordered bf16x2 hi image of W
__device__ uint32_t g_BlW[4096];   // fragment-ordered bf16x2 lo image of W
__device__ int   g_cnt[N_NODES + 1];
__device__ uint2 g_bin[(size_t)N_NODES * BIN_CAP];
__device__ int   g_spill[N_EDGES];

// ---------------------------------------------------------------------------
// helpers
// ---------------------------------------------------------------------------
__device__ __forceinline__ uint32_t pack_bf16(float a, float b) {
    __nv_bfloat162 t = __floats2bfloat162_rn(a, b);
    return *reinterpret_cast<uint32_t*>(&t);
}
__device__ __forceinline__ void bf16split(float x, float& hf, float& lf) {
    const __nv_bfloat16 h = __float2bfloat16_rn(x);
    hf = __bfloat162float(h);
    lf = x - hf;
}

// mma.sync m16n8k16 bf16: D += A*B (row.col)
__device__ __forceinline__ void mma_bf16(float* d,
                                         uint32_t a0, uint32_t a1, uint32_t a2, uint32_t a3,
                                         uint32_t b0, uint32_t b1) {
    asm volatile(
        "mma.sync.aligned.m16n8k16.row.col.f32.bf16.bf16.f32 "
        "{%0,%1,%2,%3}, {%4,%5,%6,%7}, {%8,%9}, {%0,%1,%2,%3};"
        : "+f"(d[0]), "+f"(d[1]), "+f"(d[2]), "+f"(d[3])
        : "r"(a0), "r"(a1), "r"(a2), "r"(a3), "r"(b0), "r"(b1));
}

// fma a float4-of-halfs (uint4) scaled by v into acc[8]
__device__ __forceinline__ void acc_edge(float* acc, const uint4& u, float v) {
    const float2 f0 = __half22float2(*reinterpret_cast<const __half2*>(&u.x));
    const float2 f1 = __half22float2(*reinterpret_cast<const __half2*>(&u.y));
    const float2 f2 = __half22float2(*reinterpret_cast<const __half2*>(&u.z));
    const float2 f3 = __half22float2(*reinterpret_cast<const __half2*>(&u.w));
    acc[0] = fmaf(v, f0.x, acc[0]); acc[1] = fmaf(v, f0.y, acc[1]);
    acc[2] = fmaf(v, f1.x, acc[2]); acc[3] = fmaf(v, f1.y, acc[3]);
    acc[4] = fmaf(v, f2.x, acc[4]); acc[5] = fmaf(v, f2.y, acc[5]);
    acc[6] = fmaf(v, f3.x, acc[6]); acc[7] = fmaf(v, f3.y, acc[7]);
}

// ---------------------------------------------------------------------------
// Kernel 0: W -> fragment-ordered bf16x2 hi/lo images (unchanged from R9)
// ---------------------------------------------------------------------------
__global__ __launch_bounds__(256) void gcn_wprep_kernel(const float* __restrict__ W)
{
    const int idx = blockIdx.x * 256 + threadIdx.x;   // 0..4095
    if (idx >= (D_IN / 2) * D_OUT) return;
    const int kp = idx >> 6;       // 0..63
    const int n  = idx & 63;
    const int k  = kp * 2;
    const float w0 = W[k * D_OUT + n];
    const float w1 = W[(k + 1) * D_OUT + n];
    float h0, l0, h1, l1;
    bf16split(w0, h0, l0);
    bf16split(w1, h1, l1);
    const uint32_t word = (uint32_t)((((k >> 4) * 4 + (n >> 4)) * 128)
                        + ((n & 7) * 4 + (kp & 3)) * 4
                        + ((kp >> 2) & 1) + 2 * ((n >> 3) & 1));
    g_BhW[word] = pack_bf16(h0, h1);
    g_BlW[word] = pack_bf16(l0, l1);
}

// ---------------------------------------------------------------------------
// Kernel 1: support = X @ W  (3xBF16 m16n8k16, fp16 epilogue) — unchanged R9
// ---------------------------------------------------------------------------
#define A_GROUP_W 132
#define A_BUF_BYTES (64 * A_GROUP_W * 4)
#define SM_A_HI 0
#define SM_A_LO A_BUF_BYTES
#define SM_B_HI (2 * A_BUF_BYTES)
#define SM_B_LO (2 * A_BUF_BYTES + 16384)
#define SM_TOTAL (2 * A_BUF_BYTES + 32768)   // 100352 B

__global__ void __launch_bounds__(256, 2) gcn_gemm_kernel(const float* __restrict__ X)
{
    extern __shared__ char smem[];
    uint32_t* const Ah = reinterpret_cast<uint32_t*>(smem + SM_A_HI);
    uint32_t* const Al = reinterpret_cast<uint32_t*>(smem + SM_A_LO);

    const int tid  = threadIdx.x;
    const int wid  = tid >> 5;
    const int lane = tid & 31;
    const int tileBase = blockIdx.x * TILE_M;

    {
        uint4* bh = reinterpret_cast<uint4*>(smem + SM_B_HI);
        uint4* bl = reinterpret_cast<uint4*>(smem + SM_B_LO);
        const uint4* gh = reinterpret_cast<const uint4*>(g_BhW);
        const uint4* gl = reinterpret_cast<const uint4*>(g_BlW);
        #pragma unroll
        for (int i = tid; i < 1024; i += 256) { bh[i] = gh[i]; bl[i] = gl[i]; }
    }

    {
        const float4* __restrict__ X4 = reinterpret_cast<const float4*>(X);
        #pragma unroll
        for (int it = 0; it < 16; it++) {
            const int idx = tid + it * 256;
            const int row = idx >> 5;
            const int c4  = idx & 31;
            const int node = tileBase + row;
            float4 x = make_float4(0.f, 0.f, 0.f, 0.f);
            if (node < N_NODES) x = X4[(size_t)node * 32 + c4];

            float h0, l0, h1, l1, h2, l2, h3, l3;
            bf16split(x.x, h0, l0);
            bf16split(x.y, h1, l1);
            bf16split(x.z, h2, l2);
            bf16split(x.w, h3, l3);

            const int mt = row >> 4;
            const int ks = c4 >> 2;
            const int kk = c4 & 3;
            const uint32_t word = (uint32_t)((mt * 8 + ks) * A_GROUP_W
                                + ((row & 7) * 4 + (kk & 1) * 2) * 4
                                + ((row >> 3) & 1) + 2 * (kk >> 1));
            Ah[word]     = pack_bf16(h0, h1);
            Al[word]     = pack_bf16(l0, l1);
            Ah[word + 4] = pack_bf16(h2, h3);
            Al[word + 4] = pack_bf16(l2, l3);
        }
    }
    __syncthreads();

    const int wm = wid >> 1;
    const int wn = wid & 1;

    float acc[2][4][4];
    #pragma unroll
    for (int i = 0; i < 2; i++)
        #pragma unroll
        for (int j = 0; j < 4; j++)
            #pragma unroll
            for (int q = 0; q < 4; q++) acc[i][j][q] = 0.f;

    const uint4* Ah4 = reinterpret_cast<const uint4*>(smem + SM_A_HI);
    const uint4* Al4 = reinterpret_cast<const uint4*>(smem + SM_A_LO);
    const uint4* Bh4 = reinterpret_cast<const uint4*>(smem + SM_B_HI);
    const uint4* Bl4 = reinterpret_cast<const uint4*>(smem + SM_B_LO);

    #pragma unroll
    for (int ks = 0; ks < 8; ks++) {
        uint4 ah[2], al[2], bh[2], bl[2];
        #pragma unroll
        for (int mf = 0; mf < 2; mf++) {
            const int mt = wm * 2 + mf;
            ah[mf] = Ah4[(mt * 8 + ks) * (A_GROUP_W / 4) + lane];
            al[mf] = Al4[(mt * 8 + ks) * (A_GROUP_W / 4) + lane];
        }
        #pragma unroll
        for (int p = 0; p < 2; p++) {
            const int np = wn * 2 + p;
            bh[p] = Bh4[(ks * 4 + np) * 32 + lane];
            bl[p] = Bl4[(ks * 4 + np) * 32 + lane];
        }
        #pragma unroll
        for (int mf = 0; mf < 2; mf++) {
            #pragma unroll
            for (int p = 0; p < 2; p++) {
                float* d0 = acc[mf][p * 2];
                float* d1 = acc[mf][p * 2 + 1];
                mma_bf16(d0, ah[mf].x, ah[mf].y, ah[mf].z, ah[mf].w, bh[p].x, bh[p].y);
                mma_bf16(d0, al[mf].x, al[mf].y, al[mf].z, al[mf].w, bh[p].x, bh[p].y);
                mma_bf16(d0, ah[mf].x, ah[mf].y, ah[mf].z, ah[mf].w, bl[p].x, bl[p].y);
                mma_bf16(d1, ah[mf].x, ah[mf].y, ah[mf].z, ah[mf].w, bh[p].z, bh[p].w);
                mma_bf16(d1, al[mf].x, al[mf].y, al[mf].z, al[mf].w, bh[p].z, bh[p].w);
                mma_bf16(d1, ah[mf].x, ah[mf].y, ah[mf].z, ah[mf].w, bl[p].z, bl[p].w);
            }
        }
    }

    #pragma unroll
    for (int mf = 0; mf < 2; mf++) {
        #pragma unroll
        for (int n8 = 0; n8 < 4; n8++) {
            const int col = wn * 32 + n8 * 8 + (lane & 3) * 2;
            const int row0 = tileBase + wm * 32 + mf * 16 + (lane >> 2);
            const int row1 = row0 + 8;
            if (row0 < N_NODES) {
                const __half2 h = __floats2half2_rn(acc[mf][n8][0], acc[mf][n8][1]);
                *reinterpret_cast<uint32_t*>(&g_supH[(size_t)row0 * D_OUT + col]) =
                    *reinterpret_cast<const uint32_t*>(&h);
            }
            if (row1 < N_NODES) {
                const __half2 h = __floats2half2_rn(acc[mf][n8][2], acc[mf][n8][3]);
                *reinterpret_cast<uint32_t*>(&g_supH[(size_t)row1 * D_OUT + col]) =
                    *reinterpret_cast<const uint32_t*>(&h);
            }
        }
    }
}

// ---------------------------------------------------------------------------
// Kernel 2: bin edges by destination row — 4 edges/thread, vectorized loads.
// ---------------------------------------------------------------------------
__global__ __launch_bounds__(256) void gcn_bin_kernel(
    const int* __restrict__ row, const int* __restrict__ col,
    const float* __restrict__ val)
{
    const int e0 = (blockIdx.x * 256 + threadIdx.x) * 4;
    if (e0 >= N_EDGES) return;
    const int4   r4 = *reinterpret_cast<const int4*>(row + e0);
    const int4   c4 = *reinterpret_cast<const int4*>(col + e0);
    const float4 v4 = *reinterpret_cast<const float4*>(val + e0);

    const int   rs[4] = {r4.x, r4.y, r4.z, r4.w};
    const int   cs[4] = {c4.x, c4.y, c4.z, c4.w};
    const float vs[4] = {v4.x, v4.y, v4.z, v4.w};

    #pragma unroll
    for (int j = 0; j < 4; j++) {
        const int p = atomicAdd(&g_cnt[rs[j]], 1);
        if (p < BIN_CAP) {
            g_bin[(size_t)rs[j] * BIN_CAP + p] =
                make_uint2((uint32_t)cs[j], __float_as_uint(vs[j]));
        } else {
            const int sp = atomicAdd(&g_cnt[N_NODES], 1);
            g_spill[sp] = e0 + j;
        }
    }
}

// ---------------------------------------------------------------------------
// Kernel 3: gather-reduce over fp16 support. 8 threads/node, thread t owns
// 8 cols (one uint4 of halfs per edge). 4 edges in flight per iteration.
// ---------------------------------------------------------------------------
__global__ __launch_bounds__(256) void gcn_gather_kernel(
    const float* __restrict__ bias,
    float4* __restrict__ out4)
{
    const int node = blockIdx.x * 32 + (threadIdx.x >> 3);
    const int t = threadIdx.x & 7;
    if (node >= N_NODES) return;

    const int deg = min(__ldg(&g_cnt[node]), BIN_CAP);
    const uint2* __restrict__ bin = &g_bin[(size_t)node * BIN_CAP];
    const uint4* __restrict__ sup4 = reinterpret_cast<const uint4*>(g_supH);

    float acc[8] = {0.f, 0.f, 0.f, 0.f, 0.f, 0.f, 0.f, 0.f};

    int e = 0;
    for (; e + 4 <= deg; e += 4) {
        const uint4 ba = *reinterpret_cast<const uint4*>(&bin[e]);     // edges e, e+1
        const uint4 bb = *reinterpret_cast<const uint4*>(&bin[e + 2]); // edges e+2, e+3
        const uint4 u0 = sup4[(size_t)ba.x * 8 + t];
        const uint4 u1 = sup4[(size_t)ba.z * 8 + t];
        const uint4 u2 = sup4[(size_t)bb.x * 8 + t];
        const uint4 u3 = sup4[(size_t)bb.z * 8 + t];
        acc_edge(acc, u0, __uint_as_float(ba.y));
        acc_edge(acc, u1, __uint_as_float(ba.w));
        acc_edge(acc, u2, __uint_as_float(bb.y));
        acc_edge(acc, u3, __uint_as_float(bb.w));
    }
    if (e + 2 <= deg) {
        const uint4 ba = *reinterpret_cast<const uint4*>(&bin[e]);
        const uint4 u0 = sup4[(size_t)ba.x * 8 + t];
        const uint4 u1 = sup4[(size_t)ba.z * 8 + t];
        acc_edge(acc, u0, __uint_as_float(ba.y));
        acc_edge(acc, u1, __uint_as_float(ba.w));
        e += 2;
    }
    if (e < deg) {
        const uint2 b = bin[e];
        const uint4 u = sup4[(size_t)b.x * 8 + t];
        acc_edge(acc, u, __uint_as_float(b.y));
    }

    const float4 b0 = *reinterpret_cast<const float4*>(&bias[t * 8]);
    const float4 b1 = *reinterpret_cast<const float4*>(&bias[t * 8 + 4]);
    out4[(size_t)node * 16 + t * 2] =
        make_float4(acc[0] + b0.x, acc[1] + b0.y, acc[2] + b0.z, acc[3] + b0.w);
    out4[(size_t)node * 16 + t * 2 + 1] =
        make_float4(acc[4] + b1.x, acc[5] + b1.y, acc[6] + b1.z, acc[7] + b1.w);
}

// ---------------------------------------------------------------------------
// Kernel 4: spill tail (edges beyond BIN_CAP; ~0 in practice). red.add.
// ---------------------------------------------------------------------------
__global__ __launch_bounds__(256) void gcn_spill_kernel(
    const int* __restrict__ row, const int* __restrict__ col,
    const float* __restrict__ val, float* __restrict__ out)
{
    const int n = g_cnt[N_NODES];
    const uint2* __restrict__ sup2 = reinterpret_cast<const uint2*>(g_supH);
    for (int i = blockIdx.x * 256 + threadIdx.x; i < n; i += gridDim.x * 256) {
        const int e = g_spill[i];
        const int r = __ldg(row + e);
        const int c = __ldg(col + e);
        const float v = __ldg(val + e);
        #pragma unroll
        for (int j = 0; j < 16; j++) {
            const uint2 u = sup2[(size_t)c * 16 + j];
            const float2 fa = __half22float2(*reinterpret_cast<const __half2*>(&u.x));
            const float2 fb = __half22float2(*reinterpret_cast<const __half2*>(&u.y));
            float* dst = out + (size_t)r * D_OUT + j * 4;
            asm volatile("red.global.add.v4.f32 [%0], {%1, %2, %3, %4};"
                         :: "l"(dst), "f"(fa.x * v), "f"(fa.y * v), "f"(fb.x * v), "f"(fb.y * v)
                         : "memory");
        }
    }
}

// ---------------------------------------------------------------------------
// Launch — fork/join kept: [wprep -> GEMM] || [memset -> bin], then gather+spill.
// ---------------------------------------------------------------------------
extern "C" void kernel_launch(void* const* d_in, const int* in_sizes, int n_in,
                              void* d_out, int out_size)
{
    const float* X    = (const float*)d_in[0];
    const float* W    = (const float*)d_in[1];
    const float* bias = (const float*)d_in[2];
    const int*   arow = (const int*)d_in[3];
    const int*   acol = (const int*)d_in[4];
    const float* aval = (const float*)d_in[5];
    float* out = (float*)d_out;

    int* cnt = nullptr;
    cudaGetSymbolAddress((void**)&cnt, g_cnt);

    static cudaStream_t s2 = nullptr;
    static cudaEvent_t evFork = nullptr, evJoin = nullptr;
    if (s2 == nullptr) {
        cudaStreamCreateWithFlags(&s2, cudaStreamNonBlocking);
        cudaEventCreateWithFlags(&evFork, cudaEventDisableTiming);
        cudaEventCreateWithFlags(&evJoin, cudaEventDisableTiming);
        cudaFuncSetAttribute(gcn_gemm_kernel,
                             cudaFuncAttributeMaxDynamicSharedMemorySize, SM_TOTAL);
    }

    // Fork side branch: memset(cnt) -> bin
    cudaEventRecord(evFork, 0);
    cudaStreamWaitEvent(s2, evFork, 0);
    cudaMemsetAsync(cnt, 0, (N_NODES + 1) * sizeof(int), s2);
    gcn_bin_kernel<<<(N_EDGES / 4 + 255) / 256, 256, 0, s2>>>(arow, acol, aval);
    cudaEventRecord(evJoin, s2);

    // Main branch: wprep -> GEMM
    gcn_wprep_kernel<<<((D_IN / 2) * D_OUT + 255) / 256, 256>>>(W);
    const int nTiles = (N_NODES + TILE_M - 1) / TILE_M;
    gcn_gemm_kernel<<<nTiles, 256, SM_TOTAL>>>(X);

    // Join, then gather + spill
    cudaStreamWaitEvent(0, evJoin, 0);
    gcn_gather_kernel<<<(N_NODES + 31) / 32, 256>>>(bias, (float4*)out);
    gcn_spill_kernel<<<64, 256>>>(arow, acol, aval, out);
}